// round 1
// baseline (speedup 1.0000x reference)
#include <cuda_runtime.h>
#include <math.h>

#define BB 8
#define NN 2048
#define DD 768

// Scratch (static device arrays; no allocation allowed)
__device__ float g_K[BB * NN * DD];   // row softmax of x2/x3
__device__ float g_Q[BB * NN * DD];   // col softmax of x2/x3
__device__ float g_S1[BB * DD * DD];
__device__ float g_S2[BB * DD * DD];
__device__ float g_M[BB * DD * DD];

// ---------------------------------------------------------------------------
// Row softmax over last dim (768). One block per row, 256 threads, 3 elem/thread.
// ---------------------------------------------------------------------------
__global__ void row_softmax_k(const float* __restrict__ in, float* __restrict__ out) {
    int row = blockIdx.x;
    const float* p = in + (size_t)row * DD;
    float* o = out + (size_t)row * DD;
    int t = threadIdx.x;

    float v0 = p[t], v1 = p[t + 256], v2 = p[t + 512];
    float m = fmaxf(v0, fmaxf(v1, v2));

    __shared__ float red[8];
    #pragma unroll
    for (int off = 16; off; off >>= 1)
        m = fmaxf(m, __shfl_xor_sync(0xffffffffu, m, off));
    if ((t & 31) == 0) red[t >> 5] = m;
    __syncthreads();
    float bm = red[0];
    #pragma unroll
    for (int i = 1; i < 8; i++) bm = fmaxf(bm, red[i]);

    float e0 = __expf(v0 - bm), e1 = __expf(v1 - bm), e2 = __expf(v2 - bm);
    float s = e0 + e1 + e2;
    #pragma unroll
    for (int off = 16; off; off >>= 1)
        s += __shfl_xor_sync(0xffffffffu, s, off);
    __syncthreads();                 // everyone done reading red (max)
    if ((t & 31) == 0) red[t >> 5] = s;
    __syncthreads();
    float bs = red[0];
    #pragma unroll
    for (int i = 1; i < 8; i++) bs += red[i];

    float inv = 1.0f / bs;
    o[t] = e0 * inv;
    o[t + 256] = e1 * inv;
    o[t + 512] = e2 * inv;
}

// ---------------------------------------------------------------------------
// Column softmax over token axis (N=2048) per (batch, feature).
// Block = 32 features x 8 token-lanes. Online (max,sum) then normalize pass.
// ---------------------------------------------------------------------------
__global__ void col_softmax_k(const float* __restrict__ in, float* __restrict__ out) {
    int b = blockIdx.y;
    int dl = threadIdx.x & 31;
    int d = blockIdx.x * 32 + dl;
    int lane = threadIdx.x >> 5;   // 0..7

    const float* p = in + (size_t)b * NN * DD + d;
    float m = -INFINITY, s = 0.0f;
    for (int n = lane; n < NN; n += 8) {
        float v = p[(size_t)n * DD];
        float mn = fmaxf(m, v);
        s = s * __expf(m - mn) + __expf(v - mn);
        m = mn;
    }

    __shared__ float sm[8][32], ss[8][32];
    sm[lane][dl] = m;
    ss[lane][dl] = s;
    __syncthreads();
    if (threadIdx.x < 32) {
        float M = sm[0][dl], S = ss[0][dl];
        #pragma unroll
        for (int i = 1; i < 8; i++) {
            float mi = sm[i][dl], si = ss[i][dl];
            float mn = fmaxf(M, mi);
            S = S * __expf(M - mn) + si * __expf(mi - mn);
            M = mn;
        }
        sm[0][dl] = M;
        ss[0][dl] = 1.0f / S;
    }
    __syncthreads();
    float M = sm[0][dl], invS = ss[0][dl];

    float* o = out + (size_t)b * NN * DD + d;
    for (int n = lane; n < NN; n += 8)
        o[(size_t)n * DD] = __expf(p[(size_t)n * DD] - M) * invS;
}

// ---------------------------------------------------------------------------
// S[b] = K[b]^T @ Q[b]   (A,B: [N,D] row-major; C: [D,D]; k-dim = N = 2048)
// 64x64 tile, 32 k-slice, 256 threads, 4x4 micro-tile.
// ---------------------------------------------------------------------------
__global__ void gemm_AtB_k(const float* __restrict__ A, const float* __restrict__ B,
                           float* __restrict__ C) {
    int b = blockIdx.z;
    const float* Ab = A + (size_t)b * NN * DD;
    const float* Bb = B + (size_t)b * NN * DD;
    float* Cb = C + (size_t)b * DD * DD;

    __shared__ float As[32][64], Bs[32][64];
    int tx = threadIdx.x & 15, ty = threadIdx.x >> 4;
    int d0 = blockIdx.y * 64, e0 = blockIdx.x * 64;
    float acc[4][4] = {};

    for (int kk = 0; kk < NN; kk += 32) {
        #pragma unroll
        for (int l = 0; l < 8; l++) {
            int idx = threadIdx.x + 256 * l;
            int n = idx >> 6, c = idx & 63;
            As[n][c] = Ab[(size_t)(kk + n) * DD + d0 + c];
            Bs[n][c] = Bb[(size_t)(kk + n) * DD + e0 + c];
        }
        __syncthreads();
        #pragma unroll
        for (int k = 0; k < 32; k++) {
            float4 a4 = *(const float4*)&As[k][ty * 4];
            float4 b4 = *(const float4*)&Bs[k][tx * 4];
            float av[4] = {a4.x, a4.y, a4.z, a4.w};
            float bv[4] = {b4.x, b4.y, b4.z, b4.w};
            #pragma unroll
            for (int i = 0; i < 4; i++)
                #pragma unroll
                for (int j = 0; j < 4; j++)
                    acc[i][j] += av[i] * bv[j];
        }
        __syncthreads();
    }
    #pragma unroll
    for (int i = 0; i < 4; i++)
        #pragma unroll
        for (int j = 0; j < 4; j++)
            Cb[(size_t)(d0 + ty * 4 + i) * DD + e0 + tx * 4 + j] = acc[i][j];
}

// ---------------------------------------------------------------------------
// M[b] = S1[b] @ W1^T + S2[b] @ W2^T    (all [D,D] row-major, NT gemm)
// ---------------------------------------------------------------------------
__global__ void gemm_combine_k(const float* __restrict__ S1, const float* __restrict__ S2,
                               const float* __restrict__ W1, const float* __restrict__ W2,
                               float* __restrict__ Mo) {
    int b = blockIdx.z;
    const float* S1b = S1 + (size_t)b * DD * DD;
    const float* S2b = S2 + (size_t)b * DD * DD;
    float* Mb = Mo + (size_t)b * DD * DD;

    __shared__ float As[64][33], Bs[64][33];
    int tx = threadIdx.x & 15, ty = threadIdx.x >> 4;
    int d0 = blockIdx.y * 64, e0 = blockIdx.x * 64;
    float acc[4][4] = {};

    for (int pass = 0; pass < 2; pass++) {
        const float* Sp = pass ? S2b : S1b;
        const float* Wp = pass ? W2 : W1;
        for (int kk = 0; kk < DD; kk += 32) {
            #pragma unroll
            for (int l = 0; l < 8; l++) {
                int idx = threadIdx.x + 256 * l;
                int r = idx >> 5, k = idx & 31;
                As[r][k] = Sp[(size_t)(d0 + r) * DD + kk + k];
                Bs[r][k] = Wp[(size_t)(e0 + r) * DD + kk + k];
            }
            __syncthreads();
            #pragma unroll
            for (int k = 0; k < 32; k++) {
                float av[4], bv[4];
                #pragma unroll
                for (int i = 0; i < 4; i++) {
                    av[i] = As[ty * 4 + i][k];
                    bv[i] = Bs[tx * 4 + i][k];
                }
                #pragma unroll
                for (int i = 0; i < 4; i++)
                    #pragma unroll
                    for (int j = 0; j < 4; j++)
                        acc[i][j] += av[i] * bv[j];
            }
            __syncthreads();
        }
    }
    #pragma unroll
    for (int i = 0; i < 4; i++)
        #pragma unroll
        for (int j = 0; j < 4; j++)
            Mb[(size_t)(d0 + ty * 4 + i) * DD + e0 + tx * 4 + j] = acc[i][j];
}

// ---------------------------------------------------------------------------
// out[b] = f * (x[b] @ M[b] + (b1+b2)) + x[b]   (NN gemm + fused epilogue)
// ---------------------------------------------------------------------------
__global__ void gemm_final_k(const float* __restrict__ x, const float* __restrict__ Mg,
                             const float* __restrict__ b1, const float* __restrict__ b2,
                             const float* __restrict__ w, float* __restrict__ out) {
    int b = blockIdx.z;
    const float* xb = x + (size_t)b * NN * DD;
    const float* Mb = Mg + (size_t)b * DD * DD;
    float* ob = out + (size_t)b * NN * DD;

    __shared__ float As[64][33];
    __shared__ float Bs[32][64];
    int tx = threadIdx.x & 15, ty = threadIdx.x >> 4;
    int n0 = blockIdx.y * 64, e0 = blockIdx.x * 64;
    float acc[4][4] = {};

    for (int kk = 0; kk < DD; kk += 32) {
        #pragma unroll
        for (int l = 0; l < 8; l++) {
            int idx = threadIdx.x + 256 * l;
            {
                int r = idx >> 5, k = idx & 31;
                As[r][k] = xb[(size_t)(n0 + r) * DD + kk + k];
            }
            {
                int k = idx >> 6, c = idx & 63;
                Bs[k][c] = Mb[(size_t)(kk + k) * DD + e0 + c];
            }
        }
        __syncthreads();
        #pragma unroll
        for (int k = 0; k < 32; k++) {
            float4 b4 = *(const float4*)&Bs[k][tx * 4];
            float bv[4] = {b4.x, b4.y, b4.z, b4.w};
            float av[4];
            #pragma unroll
            for (int i = 0; i < 4; i++) av[i] = As[ty * 4 + i][k];
            #pragma unroll
            for (int i = 0; i < 4; i++)
                #pragma unroll
                for (int j = 0; j < 4; j++)
                    acc[i][j] += av[i] * bv[j];
        }
        __syncthreads();
    }

    float f = 1.0f / (1.0f + __expf(-w[0]));   // sigmoid gate
    #pragma unroll
    for (int i = 0; i < 4; i++) {
        int n = n0 + ty * 4 + i;
        #pragma unroll
        for (int j = 0; j < 4; j++) {
            int e = e0 + tx * 4 + j;
            float bias = b1[e] + b2[e];
            float xv = xb[(size_t)n * DD + e];
            ob[(size_t)n * DD + e] = f * (acc[i][j] + bias) + xv;
        }
    }
}

// ---------------------------------------------------------------------------
extern "C" void kernel_launch(void* const* d_in, const int* in_sizes, int n_in,
                              void* d_out, int out_size) {
    const float* x  = (const float*)d_in[0];
    const float* x2 = (const float*)d_in[1];
    const float* x3 = (const float*)d_in[2];
    const float* W1 = (const float*)d_in[3];
    const float* b1 = (const float*)d_in[4];
    const float* W2 = (const float*)d_in[5];
    const float* b2 = (const float*)d_in[6];
    const float* w  = (const float*)d_in[7];
    float* out = (float*)d_out;

    float *K, *Q, *S1, *S2, *M;
    cudaGetSymbolAddress((void**)&K,  g_K);
    cudaGetSymbolAddress((void**)&Q,  g_Q);
    cudaGetSymbolAddress((void**)&S1, g_S1);
    cudaGetSymbolAddress((void**)&S2, g_S2);
    cudaGetSymbolAddress((void**)&M,  g_M);

    dim3 gS(DD / 64, DD / 64, BB);   // 12 x 12 x 8
    dim3 gF(DD / 64, NN / 64, BB);   // 12 x 32 x 8
    dim3 gC(DD / 32, BB);            // 24 x 8

    // Attention 1 (x2)
    row_softmax_k<<<BB * NN, 256>>>(x2, K);
    col_softmax_k<<<gC, 256>>>(x2, Q);
    gemm_AtB_k<<<gS, 256>>>(K, Q, S1);

    // Attention 2 (x3) — scratch K/Q reused (same stream, serialized)
    row_softmax_k<<<BB * NN, 256>>>(x3, K);
    col_softmax_k<<<gC, 256>>>(x3, Q);
    gemm_AtB_k<<<gS, 256>>>(K, Q, S2);

    // M = S1 @ W1^T + S2 @ W2^T
    gemm_combine_k<<<gS, 256>>>(S1, S2, W1, W2, M);

    // out = f * (x @ M + b1 + b2) + x
    gemm_final_k<<<gF, 256>>>(x, M, b1, b2, w, out);
}

// round 3
// speedup vs baseline: 1.8774x; 1.8774x over previous
#include <cuda_runtime.h>
#include <cuda_bf16.h>
#include <cstdint>
#include <math.h>

#define BB 8
#define NN 2048
#define DD 768

// ---------------- scratch (no allocation allowed) ----------------
__device__ float g_K [BB * NN * DD];
__device__ float g_Q [BB * NN * DD];
__device__ float g_Kt[BB * NN * DD];
__device__ float g_Qt[BB * NN * DD];
__device__ float g_S1[BB * DD * DD];
__device__ float g_S2[BB * DD * DD];
__device__ float g_MT[BB * DD * DD];

// ---------------------------------------------------------------------------
// Row softmax over last dim (768). One block per row, 256 threads.
// ---------------------------------------------------------------------------
__global__ void row_softmax_k(const float* __restrict__ in, float* __restrict__ out) {
    int row = blockIdx.x;
    const float* p = in + (size_t)row * DD;
    float* o = out + (size_t)row * DD;
    int t = threadIdx.x;

    float v0 = p[t], v1 = p[t + 256], v2 = p[t + 512];
    float m = fmaxf(v0, fmaxf(v1, v2));

    __shared__ float red[8];
    #pragma unroll
    for (int off = 16; off; off >>= 1)
        m = fmaxf(m, __shfl_xor_sync(0xffffffffu, m, off));
    if ((t & 31) == 0) red[t >> 5] = m;
    __syncthreads();
    float bm = red[0];
    #pragma unroll
    for (int i = 1; i < 8; i++) bm = fmaxf(bm, red[i]);

    float e0 = __expf(v0 - bm), e1 = __expf(v1 - bm), e2 = __expf(v2 - bm);
    float s = e0 + e1 + e2;
    #pragma unroll
    for (int off = 16; off; off >>= 1)
        s += __shfl_xor_sync(0xffffffffu, s, off);
    __syncthreads();
    if ((t & 31) == 0) red[t >> 5] = s;
    __syncthreads();
    float bs = red[0];
    #pragma unroll
    for (int i = 1; i < 8; i++) bs += red[i];

    float inv = 1.0f / bs;
    o[t] = e0 * inv;
    o[t + 256] = e1 * inv;
    o[t + 512] = e2 * inv;
}

// ---------------------------------------------------------------------------
// Column softmax over token axis (N=2048) per (batch, feature).
// ---------------------------------------------------------------------------
__global__ void col_softmax_k(const float* __restrict__ in, float* __restrict__ out) {
    int b = blockIdx.y;
    int dl = threadIdx.x & 31;
    int d = blockIdx.x * 32 + dl;
    int lane = threadIdx.x >> 5;

    const float* p = in + (size_t)b * NN * DD + d;
    float m = -INFINITY, s = 0.0f;
    for (int n = lane; n < NN; n += 8) {
        float v = p[(size_t)n * DD];
        float mn = fmaxf(m, v);
        s = s * __expf(m - mn) + __expf(v - mn);
        m = mn;
    }

    __shared__ float sm[8][32], ss[8][32];
    sm[lane][dl] = m;
    ss[lane][dl] = s;
    __syncthreads();
    if (threadIdx.x < 32) {
        float M = sm[0][dl], S = ss[0][dl];
        #pragma unroll
        for (int i = 1; i < 8; i++) {
            float mi = sm[i][dl], si = ss[i][dl];
            float mn = fmaxf(M, mi);
            S = S * __expf(M - mn) + si * __expf(mi - mn);
            M = mn;
        }
        sm[0][dl] = M;
        ss[0][dl] = 1.0f / S;
    }
    __syncthreads();
    float M = sm[0][dl], invS = ss[0][dl];

    float* o = out + (size_t)b * NN * DD + d;
    for (int n = lane; n < NN; n += 8)
        o[(size_t)n * DD] = __expf(p[(size_t)n * DD] - M) * invS;
}

// ---------------------------------------------------------------------------
// Transpose [b][NN][DD] -> [b][DD][NN]
// ---------------------------------------------------------------------------
__global__ void transpose_k(const float* __restrict__ in, float* __restrict__ out) {
    __shared__ float t[32][33];
    int b = blockIdx.z;
    int n0 = blockIdx.x * 32, d0 = blockIdx.y * 32;
    const float* ib = in + (size_t)b * NN * DD;
    float* ob = out + (size_t)b * NN * DD;
    int tx = threadIdx.x, ty = threadIdx.y;
    #pragma unroll
    for (int i = 0; i < 32; i += 8)
        t[ty + i][tx] = ib[(size_t)(n0 + ty + i) * DD + d0 + tx];
    __syncthreads();
    #pragma unroll
    for (int i = 0; i < 32; i += 8)
        ob[(size_t)(d0 + ty + i) * NN + n0 + tx] = t[tx][ty + i];
}

// ---------------------------------------------------------------------------
// mma.sync bf16x3-split GEMM: C[m][n] = sum_k A[m][k] * B[n][k]
// CTA tile 128x128, k-tile 32, 8 warps (warp tile 32m x 64n), double-buffered.
// fp32 -> (hi,lo) bf16 split on smem fill; acc = hi*hi + hi*lo + lo*hi (fp32).
// ---------------------------------------------------------------------------
#define TILEB  8192                 // one 128x32 bf16 sub-tile (64B rows)
#define STAGE  (4 * TILEB)          // A_hi, A_lo, B_hi, B_lo
#define SMEMSZ (2 * STAGE)          // 65536

__device__ __forceinline__ uint32_t smem_u32(const void* p) {
    uint32_t a;
    asm("{ .reg .u64 t; cvta.to.shared.u64 t, %1; cvt.u32.u64 %0, t; }" : "=r"(a) : "l"(p));
    return a;
}
__device__ __forceinline__ void ldsm4(uint32_t* r, uint32_t addr) {
    asm volatile("ldmatrix.sync.aligned.m8n8.x4.shared.b16 {%0,%1,%2,%3}, [%4];"
        : "=r"(r[0]), "=r"(r[1]), "=r"(r[2]), "=r"(r[3]) : "r"(addr));
}
__device__ __forceinline__ void mma16816(float* d, const uint32_t* a, const uint32_t* b) {
    asm volatile("mma.sync.aligned.m16n8k16.row.col.f32.bf16.bf16.f32 "
        "{%0,%1,%2,%3}, {%4,%5,%6,%7}, {%8,%9}, {%0,%1,%2,%3};"
        : "+f"(d[0]), "+f"(d[1]), "+f"(d[2]), "+f"(d[3])
        : "r"(a[0]), "r"(a[1]), "r"(a[2]), "r"(a[3]), "r"(b[0]), "r"(b[1]));
}

__device__ __forceinline__ void load16(const float* __restrict__ p, float* v) {
    #pragma unroll
    for (int j = 0; j < 4; j++) {
        float4 t = *(const float4*)(p + j * 4);
        v[j * 4] = t.x; v[j * 4 + 1] = t.y; v[j * 4 + 2] = t.z; v[j * 4 + 3] = t.w;
    }
}
// smem layout: row r (0..127) = 64B; 16B chunk c (0..3) swizzled: c ^= (r>>1)&3
__device__ __forceinline__ void store_split(char* hi, char* lo, int r, int half, const float* v) {
    #pragma unroll
    for (int j = 0; j < 2; j++) {
        uint32_t hw[4], lw[4];
        #pragma unroll
        for (int p = 0; p < 4; p++) {
            float x0 = v[j * 8 + p * 2], x1 = v[j * 8 + p * 2 + 1];
            __nv_bfloat16 h0 = __float2bfloat16_rn(x0), h1 = __float2bfloat16_rn(x1);
            __nv_bfloat16 l0 = __float2bfloat16_rn(x0 - __bfloat162float(h0));
            __nv_bfloat16 l1 = __float2bfloat16_rn(x1 - __bfloat162float(h1));
            hw[p] = (uint32_t)__bfloat16_as_ushort(h0) | ((uint32_t)__bfloat16_as_ushort(h1) << 16);
            lw[p] = (uint32_t)__bfloat16_as_ushort(l0) | ((uint32_t)__bfloat16_as_ushort(l1) << 16);
        }
        int chunk = half * 2 + j;
        int sw = chunk ^ ((r >> 1) & 3);
        uint32_t off = (uint32_t)r * 64 + (uint32_t)sw * 16;
        *(uint4*)(hi + off) = make_uint4(hw[0], hw[1], hw[2], hw[3]);
        *(uint4*)(lo + off) = make_uint4(lw[0], lw[1], lw[2], lw[3]);
    }
}

__global__ __launch_bounds__(256, 1)
void gemm_bf16x3_k(const float* __restrict__ A1, const float* __restrict__ B1, int kt1,
                   const float* __restrict__ A2, const float* __restrict__ B2, int kt2,
                   long sA1, long sB1, long sA2, long sB2,
                   int lda1, int ldb1, int lda2, int ldb2,
                   float* __restrict__ C, long sC, int ldc,
                   int mode, const float* __restrict__ bias1, const float* __restrict__ bias2,
                   const float* __restrict__ gate, const float* __restrict__ xres)
{
    extern __shared__ char sm[];
    uint32_t smb = smem_u32(sm);
    int tid = threadIdx.x, lane = tid & 31, wid = tid >> 5;
    int b = blockIdx.z, n0 = blockIdx.x * 128, m0 = blockIdx.y * 128;
    int wm = wid & 3, wn = wid >> 2;

    const float* Ab1 = A1 + (size_t)b * sA1 + (size_t)m0 * lda1;
    const float* Bb1 = B1 + (size_t)b * sB1 + (size_t)n0 * ldb1;
    const float* Ab2 = A2 ? A2 + (size_t)b * sA2 + (size_t)m0 * lda2 : (const float*)0;
    const float* Bb2 = B2 ? B2 + (size_t)b * sB2 + (size_t)n0 * ldb2 : (const float*)0;

    int r = tid >> 1, half = tid & 1;   // staging: row r, k-half (16 floats)
    int KT = kt1 + kt2;

    // ldmatrix per-lane address components
    int rA = wm * 32 + (lane & 7) + ((lane >> 3) & 1) * 8;
    int cAq = lane >> 4;
    int swA = (rA >> 1) & 3;
    int rB = wn * 64 + (lane & 7) + ((lane >> 4) & 1) * 8;
    int cBq = (lane >> 3) & 1;
    int swB = (rB >> 1) & 3;

    float acc[2][8][4] = {};
    float stA[16], stB[16];

    // prologue: tile 0
    {
        const float* As = Ab1 + half * 16;
        const float* Bs = Bb1 + half * 16;
        load16(As + (size_t)r * lda1, stA);
        load16(Bs + (size_t)r * ldb1, stB);
        store_split(sm, sm + TILEB, r, half, stA);
        store_split(sm + 2 * TILEB, sm + 3 * TILEB, r, half, stB);
    }
    __syncthreads();

    for (int kt = 0; kt < KT; kt++) {
        int buf = kt & 1;
        // prefetch next tile to regs
        if (kt + 1 < KT) {
            int k2 = kt + 1;
            const float *As, *Bs; int la, lb;
            if (k2 < kt1) { As = Ab1 + k2 * 32; Bs = Bb1 + k2 * 32; la = lda1; lb = ldb1; }
            else { As = Ab2 + (k2 - kt1) * 32; Bs = Bb2 + (k2 - kt1) * 32; la = lda2; lb = ldb2; }
            load16(As + (size_t)r * la + half * 16, stA);
            load16(Bs + (size_t)r * lb + half * 16, stB);
        }

        uint32_t bAh = smb + (uint32_t)buf * STAGE;
        uint32_t bAl = bAh + TILEB;
        uint32_t bBh = bAh + 2 * TILEB;
        uint32_t bBl = bAh + 3 * TILEB;
        #pragma unroll
        for (int ks = 0; ks < 2; ks++) {
            uint32_t aH[2][4], aL[2][4], bH[4][4], bL[4][4];
            uint32_t offA = (uint32_t)rA * 64 + (uint32_t)(((ks * 2 + cAq) ^ swA) << 4);
            #pragma unroll
            for (int mi = 0; mi < 2; mi++) {
                ldsm4(aH[mi], bAh + offA + mi * 1024);
                ldsm4(aL[mi], bAl + offA + mi * 1024);
            }
            uint32_t offB = (uint32_t)rB * 64 + (uint32_t)(((ks * 2 + cBq) ^ swB) << 4);
            #pragma unroll
            for (int np = 0; np < 4; np++) {
                ldsm4(bH[np], bBh + offB + np * 1024);
                ldsm4(bL[np], bBl + offB + np * 1024);
            }
            #pragma unroll
            for (int mi = 0; mi < 2; mi++)
                #pragma unroll
                for (int ni = 0; ni < 8; ni++) {
                    const uint32_t* bh = &bH[ni >> 1][(ni & 1) * 2];
                    const uint32_t* bl = &bL[ni >> 1][(ni & 1) * 2];
                    mma16816(acc[mi][ni], aH[mi], bh);
                    mma16816(acc[mi][ni], aH[mi], bl);
                    mma16816(acc[mi][ni], aL[mi], bh);
                }
        }

        if (kt + 1 < KT) {
            char* s2 = sm + (size_t)((kt + 1) & 1) * STAGE;
            store_split(s2, s2 + TILEB, r, half, stA);
            store_split(s2 + 2 * TILEB, s2 + 3 * TILEB, r, half, stB);
        }
        __syncthreads();
    }

    // epilogue: direct fragment stores (32B-sector aligned float2 per quad)
    int g = lane >> 2, t4 = lane & 3;
    float f = 0.0f;
    if (mode == 1) f = 1.0f / (1.0f + __expf(-gate[0]));

    #pragma unroll
    for (int mi = 0; mi < 2; mi++) {
        #pragma unroll
        for (int ni = 0; ni < 8; ni++) {
            int row0 = m0 + wm * 32 + mi * 16 + g;
            int col = n0 + wn * 64 + ni * 8 + t4 * 2;
            if (mode == 0) {
                float* p0 = C + (size_t)b * sC + (size_t)row0 * ldc + col;
                float* p1 = p0 + (size_t)8 * ldc;
                *(float2*)p0 = make_float2(acc[mi][ni][0], acc[mi][ni][1]);
                *(float2*)p1 = make_float2(acc[mi][ni][2], acc[mi][ni][3]);
            } else {
                float g1 = bias1[col] + bias2[col];
                float g2 = bias1[col + 1] + bias2[col + 1];
                const float* x0 = xres + (size_t)b * NN * DD + (size_t)row0 * DD + col;
                const float* x1 = x0 + (size_t)8 * DD;
                float2 xv0 = *(const float2*)x0;
                float2 xv1 = *(const float2*)x1;
                float* p0 = C + (size_t)b * sC + (size_t)row0 * ldc + col;
                float* p1 = p0 + (size_t)8 * ldc;
                *(float2*)p0 = make_float2(f * (acc[mi][ni][0] + g1) + xv0.x,
                                           f * (acc[mi][ni][1] + g2) + xv0.y);
                *(float2*)p1 = make_float2(f * (acc[mi][ni][2] + g1) + xv1.x,
                                           f * (acc[mi][ni][3] + g2) + xv1.y);
            }
        }
    }
}

// ---------------------------------------------------------------------------
extern "C" void kernel_launch(void* const* d_in, const int* in_sizes, int n_in,
                              void* d_out, int out_size) {
    const float* x  = (const float*)d_in[0];
    const float* x2 = (const float*)d_in[1];
    const float* x3 = (const float*)d_in[2];
    const float* W1 = (const float*)d_in[3];
    const float* b1 = (const float*)d_in[4];
    const float* W2 = (const float*)d_in[5];
    const float* b2 = (const float*)d_in[6];
    const float* w  = (const float*)d_in[7];
    float* out = (float*)d_out;

    float *K, *Q, *Kt, *Qt, *S1, *S2, *MT;
    cudaGetSymbolAddress((void**)&K,  g_K);
    cudaGetSymbolAddress((void**)&Q,  g_Q);
    cudaGetSymbolAddress((void**)&Kt, g_Kt);
    cudaGetSymbolAddress((void**)&Qt, g_Qt);
    cudaGetSymbolAddress((void**)&S1, g_S1);
    cudaGetSymbolAddress((void**)&S2, g_S2);
    cudaGetSymbolAddress((void**)&MT, g_MT);

    cudaFuncSetAttribute(gemm_bf16x3_k, cudaFuncAttributeMaxDynamicSharedMemorySize, SMEMSZ);

    dim3 gC(DD / 32, BB);
    dim3 gT(NN / 32, DD / 32, BB), bT(32, 8);
    dim3 gS(DD / 128, DD / 128, BB);   // 6 x 6 x 8
    dim3 gF(DD / 128, NN / 128, BB);   // 6 x 16 x 8

    long sTok = (long)NN * DD;
    long sDD  = (long)DD * DD;

    // Attention 1 (x2): S1[d][e] = sum_n K[n][d] * Q[n][e]
    row_softmax_k<<<BB * NN, 256>>>(x2, K);
    col_softmax_k<<<gC, 256>>>(x2, Q);
    transpose_k<<<gT, bT>>>(K, Kt);
    transpose_k<<<gT, bT>>>(Q, Qt);
    gemm_bf16x3_k<<<gS, 256, SMEMSZ>>>(Kt, Qt, NN / 32, nullptr, nullptr, 0,
                                       sTok, sTok, 0, 0, NN, NN, 0, 0,
                                       S1, sDD, DD, 0, nullptr, nullptr, nullptr, nullptr);

    // Attention 2 (x3)
    row_softmax_k<<<BB * NN, 256>>>(x3, K);
    col_softmax_k<<<gC, 256>>>(x3, Q);
    transpose_k<<<gT, bT>>>(K, Kt);
    transpose_k<<<gT, bT>>>(Q, Qt);
    gemm_bf16x3_k<<<gS, 256, SMEMSZ>>>(Kt, Qt, NN / 32, nullptr, nullptr, 0,
                                       sTok, sTok, 0, 0, NN, NN, 0, 0,
                                       S2, sDD, DD, 0, nullptr, nullptr, nullptr, nullptr);

    // MT[e][d] = sum_k W1[e][k]*S1[d][k] + W2[e][k]*S2[d][k]
    gemm_bf16x3_k<<<gS, 256, SMEMSZ>>>(W1, S1, DD / 32, W2, S2, DD / 32,
                                       0, sDD, 0, sDD, DD, DD, DD, DD,
                                       MT, sDD, DD, 0, nullptr, nullptr, nullptr, nullptr);

    // out[n][e] = f*( sum_d x[n][d]*MT[e][d] + b1[e]+b2[e] ) + x[n][e]
    gemm_bf16x3_k<<<gF, 256, SMEMSZ>>>(x, MT, DD / 32, nullptr, nullptr, 0,
                                       sTok, sDD, 0, 0, DD, DD, 0, 0,
                                       out, sTok, DD, 1, b1, b2, w, x);
}

// round 4
// speedup vs baseline: 2.3654x; 1.2600x over previous
#include <cuda_runtime.h>
#include <cuda_bf16.h>
#include <cstdint>
#include <math.h>

#define BB 8
#define NN 2048
#define DD 768

typedef __nv_bfloat16 bf16;

// ---------------- scratch (no allocation allowed) ----------------
__device__ float g_K [BB * NN * DD];
__device__ float g_Q [BB * NN * DD];
__device__ bf16  g_Kth[BB * NN * DD];
__device__ bf16  g_Ktl[BB * NN * DD];
__device__ bf16  g_Qth[BB * NN * DD];
__device__ bf16  g_Qtl[BB * NN * DD];
__device__ bf16  g_S1h[BB * DD * DD];
__device__ bf16  g_S1l[BB * DD * DD];
__device__ bf16  g_S2h[BB * DD * DD];
__device__ bf16  g_S2l[BB * DD * DD];
__device__ bf16  g_MTh[BB * DD * DD];
__device__ bf16  g_MTl[BB * DD * DD];
__device__ bf16  g_Wh [2 * DD * DD];
__device__ bf16  g_Wl [2 * DD * DD];
__device__ bf16  g_xh [BB * NN * DD];
__device__ bf16  g_xl [BB * NN * DD];

// ---------------- small helpers ----------------
__device__ __forceinline__ uint32_t smem_u32(const void* p) {
    uint32_t a;
    asm("{ .reg .u64 t; cvta.to.shared.u64 t, %1; cvt.u32.u64 %0, t; }" : "=r"(a) : "l"(p));
    return a;
}
__device__ __forceinline__ uint32_t bf_pack_split(float a, float b, uint32_t& lo) {
    __nv_bfloat16 h0 = __float2bfloat16_rn(a), h1 = __float2bfloat16_rn(b);
    __nv_bfloat16 l0 = __float2bfloat16_rn(a - __bfloat162float(h0));
    __nv_bfloat16 l1 = __float2bfloat16_rn(b - __bfloat162float(h1));
    lo = (uint32_t)__bfloat16_as_ushort(l0) | ((uint32_t)__bfloat16_as_ushort(l1) << 16);
    return (uint32_t)__bfloat16_as_ushort(h0) | ((uint32_t)__bfloat16_as_ushort(h1) << 16);
}
__device__ __forceinline__ void ldsm4(uint32_t* r, uint32_t addr) {
    asm volatile("ldmatrix.sync.aligned.m8n8.x4.shared.b16 {%0,%1,%2,%3}, [%4];"
        : "=r"(r[0]), "=r"(r[1]), "=r"(r[2]), "=r"(r[3]) : "r"(addr));
}
__device__ __forceinline__ void mma16816(float* d, const uint32_t* a, const uint32_t* b) {
    asm volatile("mma.sync.aligned.m16n8k16.row.col.f32.bf16.bf16.f32 "
        "{%0,%1,%2,%3}, {%4,%5,%6,%7}, {%8,%9}, {%0,%1,%2,%3};"
        : "+f"(d[0]), "+f"(d[1]), "+f"(d[2]), "+f"(d[3])
        : "r"(a[0]), "r"(a[1]), "r"(a[2]), "r"(a[3]), "r"(b[0]), "r"(b[1]));
}
__device__ __forceinline__ void cpa16(uint32_t dst, const void* src) {
    asm volatile("cp.async.cg.shared.global [%0], [%1], 16;" :: "r"(dst), "l"(src));
}
#define CP_COMMIT() asm volatile("cp.async.commit_group;" ::: "memory")

// ---------------------------------------------------------------------------
// Row softmax over last dim (768). One block per row, 256 threads.
// ---------------------------------------------------------------------------
__global__ void row_softmax_k(const float* __restrict__ in, float* __restrict__ out) {
    int row = blockIdx.x;
    const float* p = in + (size_t)row * DD;
    float* o = out + (size_t)row * DD;
    int t = threadIdx.x;

    float v0 = p[t], v1 = p[t + 256], v2 = p[t + 512];
    float m = fmaxf(v0, fmaxf(v1, v2));

    __shared__ float red[8];
    #pragma unroll
    for (int off = 16; off; off >>= 1)
        m = fmaxf(m, __shfl_xor_sync(0xffffffffu, m, off));
    if ((t & 31) == 0) red[t >> 5] = m;
    __syncthreads();
    float bm = red[0];
    #pragma unroll
    for (int i = 1; i < 8; i++) bm = fmaxf(bm, red[i]);

    float e0 = __expf(v0 - bm), e1 = __expf(v1 - bm), e2 = __expf(v2 - bm);
    float s = e0 + e1 + e2;
    #pragma unroll
    for (int off = 16; off; off >>= 1)
        s += __shfl_xor_sync(0xffffffffu, s, off);
    __syncthreads();
    if ((t & 31) == 0) red[t >> 5] = s;
    __syncthreads();
    float bs = red[0];
    #pragma unroll
    for (int i = 1; i < 8; i++) bs += red[i];

    float inv = 1.0f / bs;
    o[t] = e0 * inv;
    o[t + 256] = e1 * inv;
    o[t + 512] = e2 * inv;
}

// ---------------------------------------------------------------------------
// Column softmax over token axis (N=2048) per (batch, feature).
// ---------------------------------------------------------------------------
__global__ void col_softmax_k(const float* __restrict__ in, float* __restrict__ out) {
    int b = blockIdx.y;
    int dl = threadIdx.x & 31;
    int d = blockIdx.x * 32 + dl;
    int lane = threadIdx.x >> 5;

    const float* p = in + (size_t)b * NN * DD + d;
    float m = -INFINITY, s = 0.0f;
    for (int n = lane; n < NN; n += 8) {
        float v = p[(size_t)n * DD];
        float mn = fmaxf(m, v);
        s = s * __expf(m - mn) + __expf(v - mn);
        m = mn;
    }

    __shared__ float sm[8][32], ss[8][32];
    sm[lane][dl] = m;
    ss[lane][dl] = s;
    __syncthreads();
    if (threadIdx.x < 32) {
        float M = sm[0][dl], S = ss[0][dl];
        #pragma unroll
        for (int i = 1; i < 8; i++) {
            float mi = sm[i][dl], si = ss[i][dl];
            float mn = fmaxf(M, mi);
            S = S * __expf(M - mn) + si * __expf(mi - mn);
            M = mn;
        }
        sm[0][dl] = M;
        ss[0][dl] = 1.0f / S;
    }
    __syncthreads();
    float M = sm[0][dl], invS = ss[0][dl];

    float* o = out + (size_t)b * NN * DD + d;
    for (int n = lane; n < NN; n += 8)
        o[(size_t)n * DD] = __expf(p[(size_t)n * DD] - M) * invS;
}

// ---------------------------------------------------------------------------
// Transpose + split: fp32 [b][NN][DD] -> bf16 hi/lo planes [b][DD][NN]
// ---------------------------------------------------------------------------
__global__ void transpose_split_k(const float* __restrict__ in,
                                  bf16* __restrict__ hi, bf16* __restrict__ lo) {
    __shared__ float t[32][33];
    int b = blockIdx.z;
    int n0 = blockIdx.x * 32, d0 = blockIdx.y * 32;
    const float* ib = in + (size_t)b * NN * DD;
    size_t ob = (size_t)b * NN * DD;
    int tx = threadIdx.x, ty = threadIdx.y;
    #pragma unroll
    for (int i = 0; i < 32; i += 8)
        t[ty + i][tx] = ib[(size_t)(n0 + ty + i) * DD + d0 + tx];
    __syncthreads();
    #pragma unroll
    for (int i = 0; i < 32; i += 8) {
        float v = t[tx][ty + i];
        __nv_bfloat16 h = __float2bfloat16_rn(v);
        __nv_bfloat16 l = __float2bfloat16_rn(v - __bfloat162float(h));
        size_t idx = ob + (size_t)(d0 + ty + i) * NN + n0 + tx;
        hi[idx] = h;
        lo[idx] = l;
    }
}

// ---------------------------------------------------------------------------
// Elementwise split fp32 -> bf16 hi/lo (vectorized 4)
// ---------------------------------------------------------------------------
__global__ void split4_k(const float* __restrict__ in,
                         bf16* __restrict__ hi, bf16* __restrict__ lo, int n4) {
    int i = blockIdx.x * blockDim.x + threadIdx.x;
    if (i >= n4) return;
    float4 v = ((const float4*)in)[i];
    uint32_t l0, l1;
    uint32_t h0 = bf_pack_split(v.x, v.y, l0);
    uint32_t h1 = bf_pack_split(v.z, v.w, l1);
    ((uint2*)hi)[i] = make_uint2(h0, h1);
    ((uint2*)lo)[i] = make_uint2(l0, l1);
}

// ---------------------------------------------------------------------------
// mma.sync bf16x3-split GEMM, operands pre-split into bf16 hi/lo planes.
// C[m][n] = sum_k A[m][k]*B[n][k] (3-term compensated bf16)
// CTA tile 128x128, k-tile 32, 8 warps, cp.async 3-stage pipeline.
// mode 0: write C as bf16 hi/lo planes. mode 1: fp32 out = f*(acc+bias)+x.
// ---------------------------------------------------------------------------
#define TILEB  8192                 // one 128x32 bf16 plane (64B rows)
#define STAGE  (4 * TILEB)          // A_hi, A_lo, B_hi, B_lo
#define NSTG   3
#define SMEMSZ (NSTG * STAGE)       // 98304

__global__ __launch_bounds__(256, 1)
void gemm_bf16x3_k(const bf16* __restrict__ Ah1, const bf16* __restrict__ Al1,
                   const bf16* __restrict__ Bh1, const bf16* __restrict__ Bl1, int kt1,
                   const bf16* __restrict__ Ah2, const bf16* __restrict__ Al2,
                   const bf16* __restrict__ Bh2, const bf16* __restrict__ Bl2, int kt2,
                   long sA1, long sB1, long sA2, long sB2,
                   int lda1, int ldb1, int lda2, int ldb2,
                   int mode,
                   float* __restrict__ Cf, bf16* __restrict__ Ch, bf16* __restrict__ Cl,
                   long sC, int ldc,
                   const float* __restrict__ bias1, const float* __restrict__ bias2,
                   const float* __restrict__ gate, const float* __restrict__ xres)
{
    extern __shared__ char sm[];
    uint32_t smb = smem_u32(sm);
    int tid = threadIdx.x, lane = tid & 31, wid = tid >> 5;
    int b = blockIdx.z, n0 = blockIdx.x * 128, m0 = blockIdx.y * 128;
    int wm = wid & 3, wn = wid >> 2;

    const bf16* Ah1b = Ah1 + (size_t)b * sA1 + (size_t)m0 * lda1;
    const bf16* Al1b = Al1 + (size_t)b * sA1 + (size_t)m0 * lda1;
    const bf16* Bh1b = Bh1 + (size_t)b * sB1 + (size_t)n0 * ldb1;
    const bf16* Bl1b = Bl1 + (size_t)b * sB1 + (size_t)n0 * ldb1;
    const bf16* Ah2b = Ah2 ? Ah2 + (size_t)b * sA2 + (size_t)m0 * lda2 : (const bf16*)0;
    const bf16* Al2b = Al2 ? Al2 + (size_t)b * sA2 + (size_t)m0 * lda2 : (const bf16*)0;
    const bf16* Bh2b = Bh2 ? Bh2 + (size_t)b * sB2 + (size_t)n0 * ldb2 : (const bf16*)0;
    const bf16* Bl2b = Bl2 ? Bl2 + (size_t)b * sB2 + (size_t)n0 * ldb2 : (const bf16*)0;

    int KT = kt1 + kt2;

    // per-thread cp.async mapping: 2 chunks of 16B per plane
    int ch0 = tid, ch1 = tid + 256;
    int r0c = ch0 >> 2, c0c = ch0 & 3, s0c = c0c ^ ((r0c >> 1) & 3);
    int r1c = ch1 >> 2, c1c = ch1 & 3, s1c = c1c ^ ((r1c >> 1) & 3);
    uint32_t d0off = (uint32_t)r0c * 64 + (uint32_t)s0c * 16;
    uint32_t d1off = (uint32_t)r1c * 64 + (uint32_t)s1c * 16;

    #define ISSUE_STAGE(s) do {                                                      \
        int _s = (s);                                                                \
        const bf16 *ah, *al, *bh, *bl; int la, lb;                                   \
        if (_s < kt1) { ah = Ah1b + _s * 32; al = Al1b + _s * 32;                    \
                        bh = Bh1b + _s * 32; bl = Bl1b + _s * 32; la = lda1; lb = ldb1; } \
        else { int _t = _s - kt1; ah = Ah2b + _t * 32; al = Al2b + _t * 32;          \
               bh = Bh2b + _t * 32; bl = Bl2b + _t * 32; la = lda2; lb = ldb2; }     \
        uint32_t sb = smb + (uint32_t)(_s % NSTG) * STAGE;                           \
        cpa16(sb + d0off,             ah + (size_t)r0c * la + c0c * 8);              \
        cpa16(sb + d1off,             ah + (size_t)r1c * la + c1c * 8);              \
        cpa16(sb + TILEB + d0off,     al + (size_t)r0c * la + c0c * 8);              \
        cpa16(sb + TILEB + d1off,     al + (size_t)r1c * la + c1c * 8);              \
        cpa16(sb + 2*TILEB + d0off,   bh + (size_t)r0c * lb + c0c * 8);              \
        cpa16(sb + 2*TILEB + d1off,   bh + (size_t)r1c * lb + c1c * 8);              \
        cpa16(sb + 3*TILEB + d0off,   bl + (size_t)r0c * lb + c0c * 8);              \
        cpa16(sb + 3*TILEB + d1off,   bl + (size_t)r1c * lb + c1c * 8);              \
        CP_COMMIT();                                                                 \
    } while (0)

    // ldmatrix per-lane address components
    int rA = wm * 32 + (lane & 7) + ((lane >> 3) & 1) * 8;
    int cAq = lane >> 4;
    int swA = (rA >> 1) & 3;
    int rB = wn * 64 + (lane & 7) + ((lane >> 4) & 1) * 8;
    int cBq = (lane >> 3) & 1;
    int swB = (rB >> 1) & 3;

    float acc[2][8][4] = {};

    ISSUE_STAGE(0);
    ISSUE_STAGE(1);

    for (int kt = 0; kt < KT; kt++) {
        if (kt == KT - 1) asm volatile("cp.async.wait_group 0;" ::: "memory");
        else              asm volatile("cp.async.wait_group 1;" ::: "memory");
        __syncthreads();
        if (kt + 2 < KT) ISSUE_STAGE(kt + 2);

        uint32_t bAh = smb + (uint32_t)(kt % NSTG) * STAGE;
        uint32_t bAl = bAh + TILEB;
        uint32_t bBh = bAh + 2 * TILEB;
        uint32_t bBl = bAh + 3 * TILEB;
        #pragma unroll
        for (int ks = 0; ks < 2; ks++) {
            uint32_t aH[2][4], aL[2][4], bH[4][4], bL[4][4];
            uint32_t offA = (uint32_t)rA * 64 + (uint32_t)(((ks * 2 + cAq) ^ swA) << 4);
            #pragma unroll
            for (int mi = 0; mi < 2; mi++) {
                ldsm4(aH[mi], bAh + offA + mi * 1024);
                ldsm4(aL[mi], bAl + offA + mi * 1024);
            }
            uint32_t offB = (uint32_t)rB * 64 + (uint32_t)(((ks * 2 + cBq) ^ swB) << 4);
            #pragma unroll
            for (int np = 0; np < 4; np++) {
                ldsm4(bH[np], bBh + offB + np * 1024);
                ldsm4(bL[np], bBl + offB + np * 1024);
            }
            #pragma unroll
            for (int mi = 0; mi < 2; mi++)
                #pragma unroll
                for (int ni = 0; ni < 8; ni++) {
                    const uint32_t* bh = &bH[ni >> 1][(ni & 1) * 2];
                    const uint32_t* bl = &bL[ni >> 1][(ni & 1) * 2];
                    mma16816(acc[mi][ni], aH[mi], bh);
                    mma16816(acc[mi][ni], aH[mi], bl);
                    mma16816(acc[mi][ni], aL[mi], bh);
                }
        }
        __syncthreads();
    }

    // epilogue: direct fragment stores
    int g = lane >> 2, t4 = lane & 3;
    float f = 0.0f;
    if (mode == 1) f = 1.0f / (1.0f + __expf(-gate[0]));

    #pragma unroll
    for (int mi = 0; mi < 2; mi++) {
        #pragma unroll
        for (int ni = 0; ni < 8; ni++) {
            int row0 = m0 + wm * 32 + mi * 16 + g;
            int col = n0 + wn * 64 + ni * 8 + t4 * 2;
            if (mode == 0) {
                uint32_t l0, l1;
                uint32_t h0 = bf_pack_split(acc[mi][ni][0], acc[mi][ni][1], l0);
                uint32_t h1 = bf_pack_split(acc[mi][ni][2], acc[mi][ni][3], l1);
                size_t i0 = (size_t)b * sC + (size_t)row0 * ldc + col;
                size_t i1 = i0 + (size_t)8 * ldc;
                *(uint32_t*)(Ch + i0) = h0;
                *(uint32_t*)(Cl + i0) = l0;
                *(uint32_t*)(Ch + i1) = h1;
                *(uint32_t*)(Cl + i1) = l1;
            } else {
                float g1 = bias1[col] + bias2[col];
                float g2 = bias1[col + 1] + bias2[col + 1];
                const float* x0 = xres + (size_t)b * NN * DD + (size_t)row0 * DD + col;
                const float* x1 = x0 + (size_t)8 * DD;
                float2 xv0 = *(const float2*)x0;
                float2 xv1 = *(const float2*)x1;
                float* p0 = Cf + (size_t)b * sC + (size_t)row0 * ldc + col;
                float* p1 = p0 + (size_t)8 * ldc;
                *(float2*)p0 = make_float2(f * (acc[mi][ni][0] + g1) + xv0.x,
                                           f * (acc[mi][ni][1] + g2) + xv0.y);
                *(float2*)p1 = make_float2(f * (acc[mi][ni][2] + g1) + xv1.x,
                                           f * (acc[mi][ni][3] + g2) + xv1.y);
            }
        }
    }
}

// ---------------------------------------------------------------------------
extern "C" void kernel_launch(void* const* d_in, const int* in_sizes, int n_in,
                              void* d_out, int out_size) {
    const float* x  = (const float*)d_in[0];
    const float* x2 = (const float*)d_in[1];
    const float* x3 = (const float*)d_in[2];
    const float* W1 = (const float*)d_in[3];
    const float* b1 = (const float*)d_in[4];
    const float* W2 = (const float*)d_in[5];
    const float* b2 = (const float*)d_in[6];
    const float* w  = (const float*)d_in[7];
    float* out = (float*)d_out;

    float *K, *Q;
    bf16 *Kth, *Ktl, *Qth, *Qtl, *S1h, *S1l, *S2h, *S2l, *MTh, *MTl, *Wh, *Wl, *xh, *xl;
    cudaGetSymbolAddress((void**)&K,   g_K);
    cudaGetSymbolAddress((void**)&Q,   g_Q);
    cudaGetSymbolAddress((void**)&Kth, g_Kth);
    cudaGetSymbolAddress((void**)&Ktl, g_Ktl);
    cudaGetSymbolAddress((void**)&Qth, g_Qth);
    cudaGetSymbolAddress((void**)&Qtl, g_Qtl);
    cudaGetSymbolAddress((void**)&S1h, g_S1h);
    cudaGetSymbolAddress((void**)&S1l, g_S1l);
    cudaGetSymbolAddress((void**)&S2h, g_S2h);
    cudaGetSymbolAddress((void**)&S2l, g_S2l);
    cudaGetSymbolAddress((void**)&MTh, g_MTh);
    cudaGetSymbolAddress((void**)&MTl, g_MTl);
    cudaGetSymbolAddress((void**)&Wh,  g_Wh);
    cudaGetSymbolAddress((void**)&Wl,  g_Wl);
    cudaGetSymbolAddress((void**)&xh,  g_xh);
    cudaGetSymbolAddress((void**)&xl,  g_xl);

    cudaFuncSetAttribute(gemm_bf16x3_k, cudaFuncAttributeMaxDynamicSharedMemorySize, SMEMSZ);

    dim3 gC(DD / 32, BB);
    dim3 gT(NN / 32, DD / 32, BB), bT(32, 8);
    dim3 gS(DD / 128, DD / 128, BB);   // 6 x 6 x 8
    dim3 gF(DD / 128, NN / 128, BB);   // 6 x 16 x 8

    long sTok = (long)NN * DD;
    long sDD  = (long)DD * DD;

    // one-shot splits of constants & x
    split4_k<<<(2 * DD * DD / 4 + 255) / 256, 256>>>(W1, Wh, Wl, DD * DD / 4);          // W1 -> [0]
    split4_k<<<(DD * DD / 4 + 255) / 256, 256>>>(W2, Wh + (size_t)DD * DD, Wl + (size_t)DD * DD, DD * DD / 4);
    split4_k<<<(BB * NN * DD / 4 + 255) / 256, 256>>>(x, xh, xl, BB * NN * DD / 4);

    // Attention 1 (x2): S1[d][e] = sum_n K[n][d] * Q[n][e]
    row_softmax_k<<<BB * NN, 256>>>(x2, K);
    col_softmax_k<<<gC, 256>>>(x2, Q);
    transpose_split_k<<<gT, bT>>>(K, Kth, Ktl);
    transpose_split_k<<<gT, bT>>>(Q, Qth, Qtl);
    gemm_bf16x3_k<<<gS, 256, SMEMSZ>>>(Kth, Ktl, Qth, Qtl, NN / 32,
                                       nullptr, nullptr, nullptr, nullptr, 0,
                                       sTok, sTok, 0, 0, NN, NN, 0, 0,
                                       0, nullptr, S1h, S1l, sDD, DD,
                                       nullptr, nullptr, nullptr, nullptr);

    // Attention 2 (x3)
    row_softmax_k<<<BB * NN, 256>>>(x3, K);
    col_softmax_k<<<gC, 256>>>(x3, Q);
    transpose_split_k<<<gT, bT>>>(K, Kth, Ktl);
    transpose_split_k<<<gT, bT>>>(Q, Qth, Qtl);
    gemm_bf16x3_k<<<gS, 256, SMEMSZ>>>(Kth, Ktl, Qth, Qtl, NN / 32,
                                       nullptr, nullptr, nullptr, nullptr, 0,
                                       sTok, sTok, 0, 0, NN, NN, 0, 0,
                                       0, nullptr, S2h, S2l, sDD, DD,
                                       nullptr, nullptr, nullptr, nullptr);

    // MT[e][d] = sum_k W1[e][k]*S1[d][k] + W2[e][k]*S2[d][k]
    gemm_bf16x3_k<<<gS, 256, SMEMSZ>>>(Wh, Wl, S1h, S1l, DD / 32,
                                       Wh + (size_t)DD * DD, Wl + (size_t)DD * DD, S2h, S2l, DD / 32,
                                       0, sDD, 0, sDD, DD, DD, DD, DD,
                                       0, nullptr, MTh, MTl, sDD, DD,
                                       nullptr, nullptr, nullptr, nullptr);

    // out[n][e] = f*( sum_d x[n][d]*MT[e][d] + b1[e]+b2[e] ) + x[n][e]
    gemm_bf16x3_k<<<gF, 256, SMEMSZ>>>(xh, xl, MTh, MTl, DD / 32,
                                       nullptr, nullptr, nullptr, nullptr, 0,
                                       sTok, sDD, 0, 0, DD, DD, 0, 0,
                                       1, out, nullptr, nullptr, sTok, DD,
                                       b1, b2, w, x);
}

// round 5
// speedup vs baseline: 3.4542x; 1.4603x over previous
#include <cuda_runtime.h>
#include <cuda_bf16.h>
#include <cstdint>
#include <math.h>

#define BB 8
#define NN 2048
#define DD 768

typedef __nv_bfloat16 bf16;

// ---------------- scratch (no allocation allowed) ----------------
__device__ bf16 g_Kh [BB * NN * DD];
__device__ bf16 g_Qh [BB * NN * DD];
__device__ bf16 g_Ql [BB * NN * DD];
__device__ bf16 g_S1h[BB * DD * DD];
__device__ bf16 g_S1l[BB * DD * DD];
__device__ bf16 g_S2h[BB * DD * DD];
__device__ bf16 g_S2l[BB * DD * DD];
__device__ bf16 g_MTh[BB * DD * DD];
__device__ bf16 g_MTl[BB * DD * DD];
__device__ bf16 g_Wh [2 * DD * DD];
__device__ bf16 g_xh [BB * NN * DD];

// ---------------- helpers ----------------
__device__ __forceinline__ uint32_t smem_u32(const void* p) {
    uint32_t a;
    asm("{ .reg .u64 t; cvta.to.shared.u64 t, %1; cvt.u32.u64 %0, t; }" : "=r"(a) : "l"(p));
    return a;
}
__device__ __forceinline__ uint32_t bf_pack_split(float a, float b, uint32_t& lo) {
    __nv_bfloat16 h0 = __float2bfloat16_rn(a), h1 = __float2bfloat16_rn(b);
    __nv_bfloat16 l0 = __float2bfloat16_rn(a - __bfloat162float(h0));
    __nv_bfloat16 l1 = __float2bfloat16_rn(b - __bfloat162float(h1));
    lo = (uint32_t)__bfloat16_as_ushort(l0) | ((uint32_t)__bfloat16_as_ushort(l1) << 16);
    return (uint32_t)__bfloat16_as_ushort(h0) | ((uint32_t)__bfloat16_as_ushort(h1) << 16);
}
__device__ __forceinline__ void ldsm4(uint32_t* r, uint32_t addr) {
    asm volatile("ldmatrix.sync.aligned.m8n8.x4.shared.b16 {%0,%1,%2,%3}, [%4];"
        : "=r"(r[0]), "=r"(r[1]), "=r"(r[2]), "=r"(r[3]) : "r"(addr));
}
__device__ __forceinline__ void ldsm4t(uint32_t* r, uint32_t addr) {
    asm volatile("ldmatrix.sync.aligned.m8n8.x4.trans.shared.b16 {%0,%1,%2,%3}, [%4];"
        : "=r"(r[0]), "=r"(r[1]), "=r"(r[2]), "=r"(r[3]) : "r"(addr));
}
__device__ __forceinline__ void mma16816(float* d, const uint32_t* a, const uint32_t* b) {
    asm volatile("mma.sync.aligned.m16n8k16.row.col.f32.bf16.bf16.f32 "
        "{%0,%1,%2,%3}, {%4,%5,%6,%7}, {%8,%9}, {%0,%1,%2,%3};"
        : "+f"(d[0]), "+f"(d[1]), "+f"(d[2]), "+f"(d[3])
        : "r"(a[0]), "r"(a[1]), "r"(a[2]), "r"(a[3]), "r"(b[0]), "r"(b[1]));
}
__device__ __forceinline__ void cpa16(uint32_t dst, const void* src) {
    asm volatile("cp.async.cg.shared.global [%0], [%1], 16;" :: "r"(dst), "l"(src));
}
#define CP_COMMIT() asm volatile("cp.async.commit_group;" ::: "memory")

// ---------------------------------------------------------------------------
// Row softmax over last dim (768) -> bf16 hi plane only.
// ---------------------------------------------------------------------------
__global__ void row_softmax_split_k(const float* __restrict__ in, bf16* __restrict__ hi) {
    int row = blockIdx.x;
    const float* p = in + (size_t)row * DD;
    bf16* o = hi + (size_t)row * DD;
    int t = threadIdx.x;

    float v0 = p[t], v1 = p[t + 256], v2 = p[t + 512];
    float m = fmaxf(v0, fmaxf(v1, v2));

    __shared__ float red[8];
    #pragma unroll
    for (int off = 16; off; off >>= 1)
        m = fmaxf(m, __shfl_xor_sync(0xffffffffu, m, off));
    if ((t & 31) == 0) red[t >> 5] = m;
    __syncthreads();
    float bm = red[0];
    #pragma unroll
    for (int i = 1; i < 8; i++) bm = fmaxf(bm, red[i]);

    float e0 = __expf(v0 - bm), e1 = __expf(v1 - bm), e2 = __expf(v2 - bm);
    float s = e0 + e1 + e2;
    #pragma unroll
    for (int off = 16; off; off >>= 1)
        s += __shfl_xor_sync(0xffffffffu, s, off);
    __syncthreads();
    if ((t & 31) == 0) red[t >> 5] = s;
    __syncthreads();
    float bs = red[0];
    #pragma unroll
    for (int i = 1; i < 8; i++) bs += red[i];

    float inv = 1.0f / bs;
    o[t]       = __float2bfloat16_rn(e0 * inv);
    o[t + 256] = __float2bfloat16_rn(e1 * inv);
    o[t + 512] = __float2bfloat16_rn(e2 * inv);
}

// ---------------------------------------------------------------------------
// Column softmax over tokens -> bf16 hi + lo planes.
// ---------------------------------------------------------------------------
__global__ void col_softmax_split_k(const float* __restrict__ in,
                                    bf16* __restrict__ hi, bf16* __restrict__ lo) {
    int b = blockIdx.y;
    int dl = threadIdx.x & 31;
    int d = blockIdx.x * 32 + dl;
    int lane = threadIdx.x >> 5;

    const float* p = in + (size_t)b * NN * DD + d;
    float m = -INFINITY, s = 0.0f;
    for (int n = lane; n < NN; n += 8) {
        float v = p[(size_t)n * DD];
        float mn = fmaxf(m, v);
        s = s * __expf(m - mn) + __expf(v - mn);
        m = mn;
    }

    __shared__ float sm[8][32], ss[8][32];
    sm[lane][dl] = m;
    ss[lane][dl] = s;
    __syncthreads();
    if (threadIdx.x < 32) {
        float M = sm[0][dl], S = ss[0][dl];
        #pragma unroll
        for (int i = 1; i < 8; i++) {
            float mi = sm[i][dl], si = ss[i][dl];
            float mn = fmaxf(M, mi);
            S = S * __expf(M - mn) + si * __expf(mi - mn);
            M = mn;
        }
        sm[0][dl] = M;
        ss[0][dl] = 1.0f / S;
    }
    __syncthreads();
    float M = sm[0][dl], invS = ss[0][dl];

    size_t ob = (size_t)b * NN * DD + d;
    for (int n = lane; n < NN; n += 8) {
        float v = __expf(p[(size_t)n * DD] - M) * invS;
        __nv_bfloat16 h = __float2bfloat16_rn(v);
        hi[ob + (size_t)n * DD] = h;
        lo[ob + (size_t)n * DD] = __float2bfloat16_rn(v - __bfloat162float(h));
    }
}

// ---------------------------------------------------------------------------
// fp32 -> bf16 (hi only) cast, vectorized 4
// ---------------------------------------------------------------------------
__global__ void castbf_k(const float* __restrict__ in, bf16* __restrict__ hi, int n4) {
    int i = blockIdx.x * blockDim.x + threadIdx.x;
    if (i >= n4) return;
    float4 v = ((const float4*)in)[i];
    uint32_t h0 = (uint32_t)__bfloat16_as_ushort(__float2bfloat16_rn(v.x)) |
                  ((uint32_t)__bfloat16_as_ushort(__float2bfloat16_rn(v.y)) << 16);
    uint32_t h1 = (uint32_t)__bfloat16_as_ushort(__float2bfloat16_rn(v.z)) |
                  ((uint32_t)__bfloat16_as_ushort(__float2bfloat16_rn(v.w)) << 16);
    ((uint2*)hi)[i] = make_uint2(h0, h1);
}

// ---------------------------------------------------------------------------
// 2-term compensated bf16 GEMM: C[m][n] = sum_k A[m][k] * B[n][k]
//   acc = A_hi*B_hi + A_hi*B_lo    (A in plain bf16, B in bf16^2)
// CTA 128x128, k-tile 32, 8 warps (32m x 64n each), cp.async 3-stage.
// TR=false: operands k-contiguous [mn][k] (64B rows).
// TR=true : operands mn-contiguous [k][mn] (256B rows), ldmatrix.trans.
// mode 0: C -> bf16 hi/lo planes. mode 1: fp32 out = f*(acc+bias)+x.
// ---------------------------------------------------------------------------
#define TILEB  8192
#define STAGE  (3 * TILEB)          // A_hi, B_hi, B_lo
#define NSTG   3
#define SMEMSZ (NSTG * STAGE)       // 73728

template <bool TR>
__global__ __launch_bounds__(256, 1)
void gemm2t_k(const bf16* __restrict__ Ah1, const bf16* __restrict__ Bh1,
              const bf16* __restrict__ Bl1, int kt1,
              const bf16* __restrict__ Ah2, const bf16* __restrict__ Bh2,
              const bf16* __restrict__ Bl2, int kt2,
              long sA1, long sB1, long sA2, long sB2,
              int lda1, int ldb1, int lda2, int ldb2,
              int mode,
              float* __restrict__ Cf, bf16* __restrict__ Ch, bf16* __restrict__ Cl,
              long sC, int ldc,
              const float* __restrict__ bias1, const float* __restrict__ bias2,
              const float* __restrict__ gate, const float* __restrict__ xres)
{
    extern __shared__ char sm[];
    uint32_t smb = smem_u32(sm);
    int tid = threadIdx.x, lane = tid & 31, wid = tid >> 5;
    int b = blockIdx.z, n0 = blockIdx.x * 128, m0 = blockIdx.y * 128;
    int wm = wid & 3, wn = wid >> 2;

    // operand base pointers (TR: column offset; !TR: row offset)
    const bf16 *Ab1, *Bb1h, *Bb1l, *Ab2 = 0, *Bb2h = 0, *Bb2l = 0;
    if (TR) {
        Ab1  = Ah1 + (size_t)b * sA1 + m0;
        Bb1h = Bh1 + (size_t)b * sB1 + n0;
        Bb1l = Bl1 + (size_t)b * sB1 + n0;
        if (Ah2) { Ab2 = Ah2 + (size_t)b * sA2 + m0;
                   Bb2h = Bh2 + (size_t)b * sB2 + n0;
                   Bb2l = Bl2 + (size_t)b * sB2 + n0; }
    } else {
        Ab1  = Ah1 + (size_t)b * sA1 + (size_t)m0 * lda1;
        Bb1h = Bh1 + (size_t)b * sB1 + (size_t)n0 * ldb1;
        Bb1l = Bl1 + (size_t)b * sB1 + (size_t)n0 * ldb1;
        if (Ah2) { Ab2 = Ah2 + (size_t)b * sA2 + (size_t)m0 * lda2;
                   Bb2h = Bh2 + (size_t)b * sB2 + (size_t)n0 * ldb2;
                   Bb2l = Bl2 + (size_t)b * sB2 + (size_t)n0 * ldb2; }
    }
    int KT = kt1 + kt2;

    // cp.async per-thread mapping (2 chunks of 16B per plane)
    uint32_t d0off, d1off;
    int sr0, sc0, sr1, sc1;   // source row / chunk for the two chunks
    if (TR) {
        int q0 = tid, q1 = tid + 256;
        sr0 = q0 >> 4; sc0 = q0 & 15;
        sr1 = q1 >> 4; sc1 = q1 & 15;
        d0off = (uint32_t)sr0 * 256 + (uint32_t)((sc0 ^ (sr0 & 7)) << 4);
        d1off = (uint32_t)sr1 * 256 + (uint32_t)((sc1 ^ (sr1 & 7)) << 4);
    } else {
        int q0 = tid, q1 = tid + 256;
        sr0 = q0 >> 2; sc0 = q0 & 3;
        sr1 = q1 >> 2; sc1 = q1 & 3;
        d0off = (uint32_t)sr0 * 64 + (uint32_t)((sc0 ^ ((sr0 >> 1) & 3)) << 4);
        d1off = (uint32_t)sr1 * 64 + (uint32_t)((sc1 ^ ((sr1 >> 1) & 3)) << 4);
    }

    #define ISSUE_STAGE(s) do {                                                          \
        int _s = (s);                                                                    \
        const bf16 *ah, *bh, *bl; int la, lb;                                            \
        if (_s < kt1) { ah = Ab1; bh = Bb1h; bl = Bb1l; la = lda1; lb = ldb1; }          \
        else { ah = Ab2; bh = Bb2h; bl = Bb2l; la = lda2; lb = ldb2; _s -= kt1; }        \
        uint32_t sb = smb + (uint32_t)(((s) % NSTG)) * STAGE;                            \
        if (TR) {                                                                        \
            size_t kb = (size_t)(_s * 32);                                               \
            cpa16(sb + d0off,             ah + (kb + sr0) * la + sc0 * 8);               \
            cpa16(sb + d1off,             ah + (kb + sr1) * la + sc1 * 8);               \
            cpa16(sb + TILEB + d0off,     bh + (kb + sr0) * lb + sc0 * 8);               \
            cpa16(sb + TILEB + d1off,     bh + (kb + sr1) * lb + sc1 * 8);               \
            cpa16(sb + 2*TILEB + d0off,   bl + (kb + sr0) * lb + sc0 * 8);               \
            cpa16(sb + 2*TILEB + d1off,   bl + (kb + sr1) * lb + sc1 * 8);               \
        } else {                                                                         \
            int ko = _s * 32;                                                            \
            cpa16(sb + d0off,             ah + (size_t)sr0 * la + ko + sc0 * 8);         \
            cpa16(sb + d1off,             ah + (size_t)sr1 * la + ko + sc1 * 8);         \
            cpa16(sb + TILEB + d0off,     bh + (size_t)sr0 * lb + ko + sc0 * 8);         \
            cpa16(sb + TILEB + d1off,     bh + (size_t)sr1 * lb + ko + sc1 * 8);         \
            cpa16(sb + 2*TILEB + d0off,   bl + (size_t)sr0 * lb + ko + sc0 * 8);         \
            cpa16(sb + 2*TILEB + d1off,   bl + (size_t)sr1 * lb + ko + sc1 * 8);         \
        }                                                                                \
        CP_COMMIT();                                                                     \
    } while (0)

    // ldmatrix per-lane components
    int rA = 0, cAq = 0, swA = 0, rB = 0, cBq = 0, swB = 0;       // !TR
    int lrA = 0, chA0 = 0, lrB = 0, chB0 = 0, sx = 0;             // TR
    if (TR) {
        lrA  = (lane & 7) + ((lane >> 4) << 3);
        chA0 = wm * 4 + ((lane >> 3) & 1);
        lrB  = (lane & 7) + (((lane >> 3) & 1) << 3);
        chB0 = wn * 8 + ((lane >> 4) & 1);
        sx   = lane & 7;
    } else {
        rA  = wm * 32 + (lane & 7) + ((lane >> 3) & 1) * 8;
        cAq = lane >> 4;
        swA = (rA >> 1) & 3;
        rB  = wn * 64 + (lane & 7) + ((lane >> 4) & 1) * 8;
        cBq = (lane >> 3) & 1;
        swB = (rB >> 1) & 3;
    }

    float acc[2][8][4] = {};

    ISSUE_STAGE(0);
    ISSUE_STAGE(1);

    for (int kt = 0; kt < KT; kt++) {
        if (kt == KT - 1) asm volatile("cp.async.wait_group 0;" ::: "memory");
        else              asm volatile("cp.async.wait_group 1;" ::: "memory");
        __syncthreads();
        if (kt + 2 < KT) ISSUE_STAGE(kt + 2);

        uint32_t bA  = smb + (uint32_t)(kt % NSTG) * STAGE;
        uint32_t bBh = bA + TILEB;
        uint32_t bBl = bA + 2 * TILEB;
        #pragma unroll
        for (int ks = 0; ks < 2; ks++) {
            uint32_t aH[2][4], bH[4][4], bL[4][4];
            if (TR) {
                #pragma unroll
                for (int mi = 0; mi < 2; mi++)
                    ldsm4t(aH[mi], bA + (uint32_t)(lrA + ks * 16) * 256 +
                                   (uint32_t)(((chA0 + mi * 2) ^ sx) << 4));
                #pragma unroll
                for (int np = 0; np < 4; np++) {
                    uint32_t o = (uint32_t)(lrB + ks * 16) * 256 +
                                 (uint32_t)(((chB0 + np * 2) ^ sx) << 4);
                    ldsm4t(bH[np], bBh + o);
                    ldsm4t(bL[np], bBl + o);
                }
            } else {
                uint32_t offA = (uint32_t)rA * 64 + (uint32_t)(((ks * 2 + cAq) ^ swA) << 4);
                #pragma unroll
                for (int mi = 0; mi < 2; mi++)
                    ldsm4(aH[mi], bA + offA + mi * 1024);
                uint32_t offB = (uint32_t)rB * 64 + (uint32_t)(((ks * 2 + cBq) ^ swB) << 4);
                #pragma unroll
                for (int np = 0; np < 4; np++) {
                    ldsm4(bH[np], bBh + offB + np * 1024);
                    ldsm4(bL[np], bBl + offB + np * 1024);
                }
            }
            #pragma unroll
            for (int mi = 0; mi < 2; mi++)
                #pragma unroll
                for (int ni = 0; ni < 8; ni++) {
                    const uint32_t* bh = &bH[ni >> 1][(ni & 1) * 2];
                    const uint32_t* bl = &bL[ni >> 1][(ni & 1) * 2];
                    mma16816(acc[mi][ni], aH[mi], bh);
                    mma16816(acc[mi][ni], aH[mi], bl);
                }
        }
        __syncthreads();
    }

    // epilogue
    int g = lane >> 2, t4 = lane & 3;
    float f = 0.0f;
    if (mode == 1) f = 1.0f / (1.0f + __expf(-gate[0]));

    #pragma unroll
    for (int mi = 0; mi < 2; mi++) {
        #pragma unroll
        for (int ni = 0; ni < 8; ni++) {
            int row0 = m0 + wm * 32 + mi * 16 + g;
            int col = n0 + wn * 64 + ni * 8 + t4 * 2;
            if (mode == 0) {
                uint32_t l0, l1;
                uint32_t h0 = bf_pack_split(acc[mi][ni][0], acc[mi][ni][1], l0);
                uint32_t h1 = bf_pack_split(acc[mi][ni][2], acc[mi][ni][3], l1);
                size_t i0 = (size_t)b * sC + (size_t)row0 * ldc + col;
                size_t i1 = i0 + (size_t)8 * ldc;
                *(uint32_t*)(Ch + i0) = h0;
                *(uint32_t*)(Cl + i0) = l0;
                *(uint32_t*)(Ch + i1) = h1;
                *(uint32_t*)(Cl + i1) = l1;
            } else {
                float g1 = bias1[col] + bias2[col];
                float g2 = bias1[col + 1] + bias2[col + 1];
                const float* x0 = xres + (size_t)b * NN * DD + (size_t)row0 * DD + col;
                const float* x1 = x0 + (size_t)8 * DD;
                float2 xv0 = *(const float2*)x0;
                float2 xv1 = *(const float2*)x1;
                float* p0 = Cf + (size_t)b * sC + (size_t)row0 * ldc + col;
                float* p1 = p0 + (size_t)8 * ldc;
                *(float2*)p0 = make_float2(f * (acc[mi][ni][0] + g1) + xv0.x,
                                           f * (acc[mi][ni][1] + g2) + xv0.y);
                *(float2*)p1 = make_float2(f * (acc[mi][ni][2] + g1) + xv1.x,
                                           f * (acc[mi][ni][3] + g2) + xv1.y);
            }
        }
    }
    #undef ISSUE_STAGE
}

// ---------------------------------------------------------------------------
extern "C" void kernel_launch(void* const* d_in, const int* in_sizes, int n_in,
                              void* d_out, int out_size) {
    const float* x  = (const float*)d_in[0];
    const float* x2 = (const float*)d_in[1];
    const float* x3 = (const float*)d_in[2];
    const float* W1 = (const float*)d_in[3];
    const float* b1 = (const float*)d_in[4];
    const float* W2 = (const float*)d_in[5];
    const float* b2 = (const float*)d_in[6];
    const float* w  = (const float*)d_in[7];
    float* out = (float*)d_out;

    bf16 *Kh, *Qh, *Ql, *S1h, *S1l, *S2h, *S2l, *MTh, *MTl, *Wh, *xh;
    cudaGetSymbolAddress((void**)&Kh,  g_Kh);
    cudaGetSymbolAddress((void**)&Qh,  g_Qh);
    cudaGetSymbolAddress((void**)&Ql,  g_Ql);
    cudaGetSymbolAddress((void**)&S1h, g_S1h);
    cudaGetSymbolAddress((void**)&S1l, g_S1l);
    cudaGetSymbolAddress((void**)&S2h, g_S2h);
    cudaGetSymbolAddress((void**)&S2l, g_S2l);
    cudaGetSymbolAddress((void**)&MTh, g_MTh);
    cudaGetSymbolAddress((void**)&MTl, g_MTl);
    cudaGetSymbolAddress((void**)&Wh,  g_Wh);
    cudaGetSymbolAddress((void**)&xh,  g_xh);

    cudaFuncSetAttribute(gemm2t_k<true>,  cudaFuncAttributeMaxDynamicSharedMemorySize, SMEMSZ);
    cudaFuncSetAttribute(gemm2t_k<false>, cudaFuncAttributeMaxDynamicSharedMemorySize, SMEMSZ);

    dim3 gC(DD / 32, BB);
    dim3 gS(DD / 128, DD / 128, BB);   // 6 x 6 x 8
    dim3 gF(DD / 128, NN / 128, BB);   // 6 x 16 x 8

    long sTok = (long)NN * DD;
    long sDD  = (long)DD * DD;

    // one-shot bf16 casts (A-operands use hi plane only)
    castbf_k<<<(DD * DD / 4 + 255) / 256, 256>>>(W1, Wh, DD * DD / 4);
    castbf_k<<<(DD * DD / 4 + 255) / 256, 256>>>(W2, Wh + (size_t)DD * DD, DD * DD / 4);
    castbf_k<<<(BB * NN * DD / 4 + 255) / 256, 256>>>(x, xh, BB * NN * DD / 4);

    // Attention 1 (x2): S1[d][e] = sum_n K[n][d] * Q[n][e]   (TR path)
    row_softmax_split_k<<<BB * NN, 256>>>(x2, Kh);
    col_softmax_split_k<<<gC, 256>>>(x2, Qh, Ql);
    gemm2t_k<true><<<gS, 256, SMEMSZ>>>(Kh, Qh, Ql, NN / 32,
                                        nullptr, nullptr, nullptr, 0,
                                        sTok, sTok, 0, 0, DD, DD, 0, 0,
                                        0, nullptr, S1h, S1l, sDD, DD,
                                        nullptr, nullptr, nullptr, nullptr);

    // Attention 2 (x3) — reuse Kh/Qh/Ql
    row_softmax_split_k<<<BB * NN, 256>>>(x3, Kh);
    col_softmax_split_k<<<gC, 256>>>(x3, Qh, Ql);
    gemm2t_k<true><<<gS, 256, SMEMSZ>>>(Kh, Qh, Ql, NN / 32,
                                        nullptr, nullptr, nullptr, 0,
                                        sTok, sTok, 0, 0, DD, DD, 0, 0,
                                        0, nullptr, S2h, S2l, sDD, DD,
                                        nullptr, nullptr, nullptr, nullptr);

    // MT[e][d] = sum_k W1[e][k]*S1[d][k] + W2[e][k]*S2[d][k]   (non-TR)
    gemm2t_k<false><<<gS, 256, SMEMSZ>>>(Wh, S1h, S1l, DD / 32,
                                         Wh + (size_t)DD * DD, S2h, S2l, DD / 32,
                                         0, sDD, 0, sDD, DD, DD, DD, DD,
                                         0, nullptr, MTh, MTl, sDD, DD,
                                         nullptr, nullptr, nullptr, nullptr);

    // out[n][e] = f*( sum_d x[n][d]*MT[e][d] + b1[e]+b2[e] ) + x[n][e]   (non-TR)
    gemm2t_k<false><<<gF, 256, SMEMSZ>>>(xh, MTh, MTl, DD / 32,
                                         nullptr, nullptr, nullptr, 0,
                                         sTok, sDD, 0, 0, DD, DD, 0, 0,
                                         1, out, nullptr, nullptr, sTok, DD,
                                         b1, b2, w, x);
}

// round 6
// speedup vs baseline: 5.6584x; 1.6381x over previous
#include <cuda_runtime.h>
#include <cuda_bf16.h>
#include <cstdint>
#include <math.h>

#define BB 8
#define NN 2048
#define DD 768

typedef __nv_bfloat16 bf16;

// ---------------- scratch (no allocation allowed) ----------------
__device__ bf16 g_Kh [BB * NN * DD];
__device__ bf16 g_Qh [BB * NN * DD];
__device__ bf16 g_S1h[BB * DD * DD];
__device__ bf16 g_S2h[BB * DD * DD];
__device__ bf16 g_MTh[BB * DD * DD];
__device__ bf16 g_Wh [2 * DD * DD];
__device__ bf16 g_xh [BB * NN * DD];

// ---------------- helpers ----------------
__device__ __forceinline__ uint32_t smem_u32(const void* p) {
    uint32_t a;
    asm("{ .reg .u64 t; cvta.to.shared.u64 t, %1; cvt.u32.u64 %0, t; }" : "=r"(a) : "l"(p));
    return a;
}
__device__ __forceinline__ void ldsm4(uint32_t* r, uint32_t addr) {
    asm volatile("ldmatrix.sync.aligned.m8n8.x4.shared.b16 {%0,%1,%2,%3}, [%4];"
        : "=r"(r[0]), "=r"(r[1]), "=r"(r[2]), "=r"(r[3]) : "r"(addr));
}
__device__ __forceinline__ void ldsm4t(uint32_t* r, uint32_t addr) {
    asm volatile("ldmatrix.sync.aligned.m8n8.x4.trans.shared.b16 {%0,%1,%2,%3}, [%4];"
        : "=r"(r[0]), "=r"(r[1]), "=r"(r[2]), "=r"(r[3]) : "r"(addr));
}
__device__ __forceinline__ void mma16816(float* d, const uint32_t* a, const uint32_t* b) {
    asm volatile("mma.sync.aligned.m16n8k16.row.col.f32.bf16.bf16.f32 "
        "{%0,%1,%2,%3}, {%4,%5,%6,%7}, {%8,%9}, {%0,%1,%2,%3};"
        : "+f"(d[0]), "+f"(d[1]), "+f"(d[2]), "+f"(d[3])
        : "r"(a[0]), "r"(a[1]), "r"(a[2]), "r"(a[3]), "r"(b[0]), "r"(b[1]));
}
__device__ __forceinline__ void cpa16(uint32_t dst, const void* src) {
    asm volatile("cp.async.cg.shared.global [%0], [%1], 16;" :: "r"(dst), "l"(src));
}
#define CP_COMMIT() asm volatile("cp.async.commit_group;" ::: "memory")

// ---------------------------------------------------------------------------
// Row softmax over last dim (768) -> bf16.
// ---------------------------------------------------------------------------
__global__ void row_softmax_split_k(const float* __restrict__ in, bf16* __restrict__ hi) {
    int row = blockIdx.x;
    const float* p = in + (size_t)row * DD;
    bf16* o = hi + (size_t)row * DD;
    int t = threadIdx.x;

    float v0 = p[t], v1 = p[t + 256], v2 = p[t + 512];
    float m = fmaxf(v0, fmaxf(v1, v2));

    __shared__ float red[8];
    #pragma unroll
    for (int off = 16; off; off >>= 1)
        m = fmaxf(m, __shfl_xor_sync(0xffffffffu, m, off));
    if ((t & 31) == 0) red[t >> 5] = m;
    __syncthreads();
    float bm = red[0];
    #pragma unroll
    for (int i = 1; i < 8; i++) bm = fmaxf(bm, red[i]);

    float e0 = __expf(v0 - bm), e1 = __expf(v1 - bm), e2 = __expf(v2 - bm);
    float s = e0 + e1 + e2;
    #pragma unroll
    for (int off = 16; off; off >>= 1)
        s += __shfl_xor_sync(0xffffffffu, s, off);
    __syncthreads();
    if ((t & 31) == 0) red[t >> 5] = s;
    __syncthreads();
    float bs = red[0];
    #pragma unroll
    for (int i = 1; i < 8; i++) bs += red[i];

    float inv = 1.0f / bs;
    o[t]       = __float2bfloat16_rn(e0 * inv);
    o[t + 256] = __float2bfloat16_rn(e1 * inv);
    o[t + 512] = __float2bfloat16_rn(e2 * inv);
}

// ---------------------------------------------------------------------------
// Column softmax over tokens -> bf16.
// ---------------------------------------------------------------------------
__global__ void col_softmax_split_k(const float* __restrict__ in, bf16* __restrict__ hi) {
    int b = blockIdx.y;
    int dl = threadIdx.x & 31;
    int d = blockIdx.x * 32 + dl;
    int lane = threadIdx.x >> 5;

    const float* p = in + (size_t)b * NN * DD + d;
    float m = -INFINITY, s = 0.0f;
    for (int n = lane; n < NN; n += 8) {
        float v = p[(size_t)n * DD];
        float mn = fmaxf(m, v);
        s = s * __expf(m - mn) + __expf(v - mn);
        m = mn;
    }

    __shared__ float sm[8][32], ss[8][32];
    sm[lane][dl] = m;
    ss[lane][dl] = s;
    __syncthreads();
    if (threadIdx.x < 32) {
        float M = sm[0][dl], S = ss[0][dl];
        #pragma unroll
        for (int i = 1; i < 8; i++) {
            float mi = sm[i][dl], si = ss[i][dl];
            float mn = fmaxf(M, mi);
            S = S * __expf(M - mn) + si * __expf(mi - mn);
            M = mn;
        }
        sm[0][dl] = M;
        ss[0][dl] = 1.0f / S;
    }
    __syncthreads();
    float M = sm[0][dl], invS = ss[0][dl];

    size_t ob = (size_t)b * NN * DD + d;
    for (int n = lane; n < NN; n += 8)
        hi[ob + (size_t)n * DD] = __float2bfloat16_rn(__expf(p[(size_t)n * DD] - M) * invS);
}

// ---------------------------------------------------------------------------
// fp32 -> bf16 cast, vectorized 4
// ---------------------------------------------------------------------------
__global__ void castbf_k(const float* __restrict__ in, bf16* __restrict__ hi, int n4) {
    int i = blockIdx.x * blockDim.x + threadIdx.x;
    if (i >= n4) return;
    float4 v = ((const float4*)in)[i];
    uint32_t h0 = (uint32_t)__bfloat16_as_ushort(__float2bfloat16_rn(v.x)) |
                  ((uint32_t)__bfloat16_as_ushort(__float2bfloat16_rn(v.y)) << 16);
    uint32_t h1 = (uint32_t)__bfloat16_as_ushort(__float2bfloat16_rn(v.z)) |
                  ((uint32_t)__bfloat16_as_ushort(__float2bfloat16_rn(v.w)) << 16);
    ((uint2*)hi)[i] = make_uint2(h0, h1);
}

// ---------------------------------------------------------------------------
// Single-term bf16 GEMM: C[m][n] = sum_k A[m][k] * B[n][k]  (fp32 accum)
// CTA 128x128, k-tile 32, 8 warps (32m x 64n each), cp.async 3-stage.
// TR=false: operands k-contiguous [mn][k]. TR=true: [k][mn] via ldmatrix.trans.
// mode 0: C -> bf16. mode 1: fp32 out = f*(acc+bias)+x.
// ---------------------------------------------------------------------------
#define TILEB  8192
#define STAGE  (2 * TILEB)          // A, B
#define NSTG   3
#define SMEMSZ (NSTG * STAGE)       // 49152

template <bool TR>
__global__ __launch_bounds__(256, 2)
void gemm1t_k(const bf16* __restrict__ Ah1, const bf16* __restrict__ Bh1, int kt1,
              const bf16* __restrict__ Ah2, const bf16* __restrict__ Bh2, int kt2,
              long sA1, long sB1, long sA2, long sB2,
              int lda1, int ldb1, int lda2, int ldb2,
              int mode,
              float* __restrict__ Cf, bf16* __restrict__ Ch,
              long sC, int ldc,
              const float* __restrict__ bias1, const float* __restrict__ bias2,
              const float* __restrict__ gate, const float* __restrict__ xres)
{
    extern __shared__ char sm[];
    uint32_t smb = smem_u32(sm);
    int tid = threadIdx.x, lane = tid & 31, wid = tid >> 5;
    int b = blockIdx.z, n0 = blockIdx.x * 128, m0 = blockIdx.y * 128;
    int wm = wid & 3, wn = wid >> 2;

    const bf16 *Ab1, *Bb1, *Ab2 = 0, *Bb2 = 0;
    if (TR) {
        Ab1 = Ah1 + (size_t)b * sA1 + m0;
        Bb1 = Bh1 + (size_t)b * sB1 + n0;
        if (Ah2) { Ab2 = Ah2 + (size_t)b * sA2 + m0; Bb2 = Bh2 + (size_t)b * sB2 + n0; }
    } else {
        Ab1 = Ah1 + (size_t)b * sA1 + (size_t)m0 * lda1;
        Bb1 = Bh1 + (size_t)b * sB1 + (size_t)n0 * ldb1;
        if (Ah2) { Ab2 = Ah2 + (size_t)b * sA2 + (size_t)m0 * lda2;
                   Bb2 = Bh2 + (size_t)b * sB2 + (size_t)n0 * ldb2; }
    }
    int KT = kt1 + kt2;

    // cp.async per-thread mapping (2 chunks of 16B per plane)
    uint32_t d0off, d1off;
    int sr0, sc0, sr1, sc1;
    if (TR) {
        int q0 = tid, q1 = tid + 256;
        sr0 = q0 >> 4; sc0 = q0 & 15;
        sr1 = q1 >> 4; sc1 = q1 & 15;
        d0off = (uint32_t)sr0 * 256 + (uint32_t)((sc0 ^ (sr0 & 7)) << 4);
        d1off = (uint32_t)sr1 * 256 + (uint32_t)((sc1 ^ (sr1 & 7)) << 4);
    } else {
        int q0 = tid, q1 = tid + 256;
        sr0 = q0 >> 2; sc0 = q0 & 3;
        sr1 = q1 >> 2; sc1 = q1 & 3;
        d0off = (uint32_t)sr0 * 64 + (uint32_t)((sc0 ^ ((sr0 >> 1) & 3)) << 4);
        d1off = (uint32_t)sr1 * 64 + (uint32_t)((sc1 ^ ((sr1 >> 1) & 3)) << 4);
    }

    #define ISSUE_STAGE(s) do {                                                          \
        int _s = (s);                                                                    \
        const bf16 *ah, *bh; int la, lb;                                                 \
        if (_s < kt1) { ah = Ab1; bh = Bb1; la = lda1; lb = ldb1; }                      \
        else { ah = Ab2; bh = Bb2; la = lda2; lb = ldb2; _s -= kt1; }                    \
        uint32_t sb = smb + (uint32_t)(((s) % NSTG)) * STAGE;                            \
        if (TR) {                                                                        \
            size_t kb = (size_t)(_s * 32);                                               \
            cpa16(sb + d0off,         ah + (kb + sr0) * la + sc0 * 8);                   \
            cpa16(sb + d1off,         ah + (kb + sr1) * la + sc1 * 8);                   \
            cpa16(sb + TILEB + d0off, bh + (kb + sr0) * lb + sc0 * 8);                   \
            cpa16(sb + TILEB + d1off, bh + (kb + sr1) * lb + sc1 * 8);                   \
        } else {                                                                         \
            int ko = _s * 32;                                                            \
            cpa16(sb + d0off,         ah + (size_t)sr0 * la + ko + sc0 * 8);             \
            cpa16(sb + d1off,         ah + (size_t)sr1 * la + ko + sc1 * 8);             \
            cpa16(sb + TILEB + d0off, bh + (size_t)sr0 * lb + ko + sc0 * 8);             \
            cpa16(sb + TILEB + d1off, bh + (size_t)sr1 * lb + ko + sc1 * 8);             \
        }                                                                                \
        CP_COMMIT();                                                                     \
    } while (0)

    // ldmatrix per-lane components
    int rA = 0, cAq = 0, swA = 0, rB = 0, cBq = 0, swB = 0;       // !TR
    int lrA = 0, chA0 = 0, lrB = 0, chB0 = 0, sx = 0;             // TR
    if (TR) {
        lrA  = (lane & 7) + ((lane >> 4) << 3);
        chA0 = wm * 4 + ((lane >> 3) & 1);
        lrB  = (lane & 7) + (((lane >> 3) & 1) << 3);
        chB0 = wn * 8 + ((lane >> 4) & 1);
        sx   = lane & 7;
    } else {
        rA  = wm * 32 + (lane & 7) + ((lane >> 3) & 1) * 8;
        cAq = lane >> 4;
        swA = (rA >> 1) & 3;
        rB  = wn * 64 + (lane & 7) + ((lane >> 4) & 1) * 8;
        cBq = (lane >> 3) & 1;
        swB = (rB >> 1) & 3;
    }

    float acc[2][8][4] = {};

    ISSUE_STAGE(0);
    ISSUE_STAGE(1);

    for (int kt = 0; kt < KT; kt++) {
        if (kt == KT - 1) asm volatile("cp.async.wait_group 0;" ::: "memory");
        else              asm volatile("cp.async.wait_group 1;" ::: "memory");
        __syncthreads();
        if (kt + 2 < KT) ISSUE_STAGE(kt + 2);

        uint32_t bA = smb + (uint32_t)(kt % NSTG) * STAGE;
        uint32_t bB = bA + TILEB;
        #pragma unroll
        for (int ks = 0; ks < 2; ks++) {
            uint32_t aH[2][4], bH[4][4];
            if (TR) {
                #pragma unroll
                for (int mi = 0; mi < 2; mi++)
                    ldsm4t(aH[mi], bA + (uint32_t)(lrA + ks * 16) * 256 +
                                   (uint32_t)(((chA0 + mi * 2) ^ sx) << 4));
                #pragma unroll
                for (int np = 0; np < 4; np++)
                    ldsm4t(bH[np], bB + (uint32_t)(lrB + ks * 16) * 256 +
                                   (uint32_t)(((chB0 + np * 2) ^ sx) << 4));
            } else {
                uint32_t offA = (uint32_t)rA * 64 + (uint32_t)(((ks * 2 + cAq) ^ swA) << 4);
                #pragma unroll
                for (int mi = 0; mi < 2; mi++)
                    ldsm4(aH[mi], bA + offA + mi * 1024);
                uint32_t offB = (uint32_t)rB * 64 + (uint32_t)(((ks * 2 + cBq) ^ swB) << 4);
                #pragma unroll
                for (int np = 0; np < 4; np++)
                    ldsm4(bH[np], bB + offB + np * 1024);
            }
            #pragma unroll
            for (int mi = 0; mi < 2; mi++)
                #pragma unroll
                for (int ni = 0; ni < 8; ni++)
                    mma16816(acc[mi][ni], aH[mi], &bH[ni >> 1][(ni & 1) * 2]);
        }
        __syncthreads();
    }

    // epilogue
    int g = lane >> 2, t4 = lane & 3;
    float f = 0.0f;
    if (mode == 1) f = 1.0f / (1.0f + __expf(-gate[0]));

    #pragma unroll
    for (int mi = 0; mi < 2; mi++) {
        #pragma unroll
        for (int ni = 0; ni < 8; ni++) {
            int row0 = m0 + wm * 32 + mi * 16 + g;
            int col = n0 + wn * 64 + ni * 8 + t4 * 2;
            if (mode == 0) {
                uint32_t h0 = (uint32_t)__bfloat16_as_ushort(__float2bfloat16_rn(acc[mi][ni][0])) |
                              ((uint32_t)__bfloat16_as_ushort(__float2bfloat16_rn(acc[mi][ni][1])) << 16);
                uint32_t h1 = (uint32_t)__bfloat16_as_ushort(__float2bfloat16_rn(acc[mi][ni][2])) |
                              ((uint32_t)__bfloat16_as_ushort(__float2bfloat16_rn(acc[mi][ni][3])) << 16);
                size_t i0 = (size_t)b * sC + (size_t)row0 * ldc + col;
                size_t i1 = i0 + (size_t)8 * ldc;
                *(uint32_t*)(Ch + i0) = h0;
                *(uint32_t*)(Ch + i1) = h1;
            } else {
                float g1 = bias1[col] + bias2[col];
                float g2 = bias1[col + 1] + bias2[col + 1];
                const float* x0 = xres + (size_t)b * NN * DD + (size_t)row0 * DD + col;
                const float* x1 = x0 + (size_t)8 * DD;
                float2 xv0 = *(const float2*)x0;
                float2 xv1 = *(const float2*)x1;
                float* p0 = Cf + (size_t)b * sC + (size_t)row0 * ldc + col;
                float* p1 = p0 + (size_t)8 * ldc;
                *(float2*)p0 = make_float2(f * (acc[mi][ni][0] + g1) + xv0.x,
                                           f * (acc[mi][ni][1] + g2) + xv0.y);
                *(float2*)p1 = make_float2(f * (acc[mi][ni][2] + g1) + xv1.x,
                                           f * (acc[mi][ni][3] + g2) + xv1.y);
            }
        }
    }
    #undef ISSUE_STAGE
}

// ---------------------------------------------------------------------------
extern "C" void kernel_launch(void* const* d_in, const int* in_sizes, int n_in,
                              void* d_out, int out_size) {
    const float* x  = (const float*)d_in[0];
    const float* x2 = (const float*)d_in[1];
    const float* x3 = (const float*)d_in[2];
    const float* W1 = (const float*)d_in[3];
    const float* b1 = (const float*)d_in[4];
    const float* W2 = (const float*)d_in[5];
    const float* b2 = (const float*)d_in[6];
    const float* w  = (const float*)d_in[7];
    float* out = (float*)d_out;

    bf16 *Kh, *Qh, *S1h, *S2h, *MTh, *Wh, *xh;
    cudaGetSymbolAddress((void**)&Kh,  g_Kh);
    cudaGetSymbolAddress((void**)&Qh,  g_Qh);
    cudaGetSymbolAddress((void**)&S1h, g_S1h);
    cudaGetSymbolAddress((void**)&S2h, g_S2h);
    cudaGetSymbolAddress((void**)&MTh, g_MTh);
    cudaGetSymbolAddress((void**)&Wh,  g_Wh);
    cudaGetSymbolAddress((void**)&xh,  g_xh);

    cudaFuncSetAttribute(gemm1t_k<true>,  cudaFuncAttributeMaxDynamicSharedMemorySize, SMEMSZ);
    cudaFuncSetAttribute(gemm1t_k<false>, cudaFuncAttributeMaxDynamicSharedMemorySize, SMEMSZ);

    dim3 gC(DD / 32, BB);
    dim3 gS(DD / 128, DD / 128, BB);   // 6 x 6 x 8
    dim3 gF(DD / 128, NN / 128, BB);   // 6 x 16 x 8

    long sTok = (long)NN * DD;
    long sDD  = (long)DD * DD;

    // one-shot bf16 casts
    castbf_k<<<(DD * DD / 4 + 255) / 256, 256>>>(W1, Wh, DD * DD / 4);
    castbf_k<<<(DD * DD / 4 + 255) / 256, 256>>>(W2, Wh + (size_t)DD * DD, DD * DD / 4);
    castbf_k<<<(BB * NN * DD / 4 + 255) / 256, 256>>>(x, xh, BB * NN * DD / 4);

    // Attention 1 (x2): S1[d][e] = sum_n K[n][d] * Q[n][e]   (TR path)
    row_softmax_split_k<<<BB * NN, 256>>>(x2, Kh);
    col_softmax_split_k<<<gC, 256>>>(x2, Qh);
    gemm1t_k<true><<<gS, 256, SMEMSZ>>>(Kh, Qh, NN / 32, nullptr, nullptr, 0,
                                        sTok, sTok, 0, 0, DD, DD, 0, 0,
                                        0, nullptr, S1h, sDD, DD,
                                        nullptr, nullptr, nullptr, nullptr);

    // Attention 2 (x3) — reuse Kh/Qh
    row_softmax_split_k<<<BB * NN, 256>>>(x3, Kh);
    col_softmax_split_k<<<gC, 256>>>(x3, Qh);
    gemm1t_k<true><<<gS, 256, SMEMSZ>>>(Kh, Qh, NN / 32, nullptr, nullptr, 0,
                                        sTok, sTok, 0, 0, DD, DD, 0, 0,
                                        0, nullptr, S2h, sDD, DD,
                                        nullptr, nullptr, nullptr, nullptr);

    // MT[e][d] = sum_k W1[e][k]*S1[d][k] + W2[e][k]*S2[d][k]   (non-TR)
    gemm1t_k<false><<<gS, 256, SMEMSZ>>>(Wh, S1h, DD / 32,
                                         Wh + (size_t)DD * DD, S2h, DD / 32,
                                         0, sDD, 0, sDD, DD, DD, DD, DD,
                                         0, nullptr, MTh, sDD, DD,
                                         nullptr, nullptr, nullptr, nullptr);

    // out[n][e] = f*( sum_d x[n][d]*MT[e][d] + b1[e]+b2[e] ) + x[n][e]   (non-TR)
    gemm1t_k<false><<<gF, 256, SMEMSZ>>>(xh, MTh, DD / 32, nullptr, nullptr, 0,
                                         sTok, sDD, 0, 0, DD, DD, 0, 0,
                                         1, out, nullptr, sTok, DD,
                                         b1, b2, w, x);
}

// round 7
// speedup vs baseline: 5.9607x; 1.0534x over previous
#include <cuda_runtime.h>
#include <cuda_bf16.h>
#include <cstdint>
#include <math.h>

#define BB 8
#define NN 2048
#define DD 768

typedef __nv_bfloat16 bf16;

// ---------------- scratch (no allocation allowed) ----------------
__device__ bf16 g_K2h[BB * NN * DD];
__device__ bf16 g_Q2h[BB * NN * DD];
__device__ bf16 g_K3h[BB * NN * DD];
__device__ bf16 g_Q3h[BB * NN * DD];
__device__ bf16 g_S1h[BB * DD * DD];
__device__ bf16 g_S2h[BB * DD * DD];
__device__ bf16 g_MTh[BB * DD * DD];
__device__ bf16 g_Wh [2 * DD * DD];
__device__ bf16 g_xh [BB * NN * DD];

// ---------------- helpers ----------------
__device__ __forceinline__ uint32_t smem_u32(const void* p) {
    uint32_t a;
    asm("{ .reg .u64 t; cvta.to.shared.u64 t, %1; cvt.u32.u64 %0, t; }" : "=r"(a) : "l"(p));
    return a;
}
__device__ __forceinline__ void ldsm4(uint32_t* r, uint32_t addr) {
    asm volatile("ldmatrix.sync.aligned.m8n8.x4.shared.b16 {%0,%1,%2,%3}, [%4];"
        : "=r"(r[0]), "=r"(r[1]), "=r"(r[2]), "=r"(r[3]) : "r"(addr));
}
__device__ __forceinline__ void ldsm4t(uint32_t* r, uint32_t addr) {
    asm volatile("ldmatrix.sync.aligned.m8n8.x4.trans.shared.b16 {%0,%1,%2,%3}, [%4];"
        : "=r"(r[0]), "=r"(r[1]), "=r"(r[2]), "=r"(r[3]) : "r"(addr));
}
__device__ __forceinline__ void mma16816(float* d, const uint32_t* a, const uint32_t* b) {
    asm volatile("mma.sync.aligned.m16n8k16.row.col.f32.bf16.bf16.f32 "
        "{%0,%1,%2,%3}, {%4,%5,%6,%7}, {%8,%9}, {%0,%1,%2,%3};"
        : "+f"(d[0]), "+f"(d[1]), "+f"(d[2]), "+f"(d[3])
        : "r"(a[0]), "r"(a[1]), "r"(a[2]), "r"(a[3]), "r"(b[0]), "r"(b[1]));
}
__device__ __forceinline__ void cpa16(uint32_t dst, const void* src) {
    asm volatile("cp.async.cg.shared.global [%0], [%1], 16;" :: "r"(dst), "l"(src));
}
#define CP_COMMIT() asm volatile("cp.async.commit_group;" ::: "memory")

__device__ __forceinline__ uint32_t pack_bf2(float a, float b) {
    return (uint32_t)__bfloat16_as_ushort(__float2bfloat16_rn(a)) |
           ((uint32_t)__bfloat16_as_ushort(__float2bfloat16_rn(b)) << 16);
}

// ---------------------------------------------------------------------------
// Row softmax, warp-per-row, fused over two tensors. 8 warps / 256 thr per blk.
// Each lane: 6 float4 (24 values) of the 768-float row.
// ---------------------------------------------------------------------------
__global__ void row_softmax2_k(const float* __restrict__ in2, bf16* __restrict__ o2,
                               const float* __restrict__ in3, bf16* __restrict__ o3) {
    int gw = blockIdx.x * 8 + (threadIdx.x >> 5);   // global warp id
    int lane = threadIdx.x & 31;
    const int nrows = BB * NN;
    const float* in = (gw < nrows) ? in2 : in3;
    bf16* out = (gw < nrows) ? o2 : o3;
    int row = (gw < nrows) ? gw : gw - nrows;

    const float* p = in + (size_t)row * DD;
    float4 v[6];
    #pragma unroll
    for (int j = 0; j < 6; j++) v[j] = *(const float4*)(p + (j * 32 + lane) * 4);

    float m = -INFINITY;
    #pragma unroll
    for (int j = 0; j < 6; j++)
        m = fmaxf(m, fmaxf(fmaxf(v[j].x, v[j].y), fmaxf(v[j].z, v[j].w)));
    #pragma unroll
    for (int off = 16; off; off >>= 1)
        m = fmaxf(m, __shfl_xor_sync(0xffffffffu, m, off));

    float e[6][4];
    float s = 0.0f;
    #pragma unroll
    for (int j = 0; j < 6; j++) {
        e[j][0] = __expf(v[j].x - m); e[j][1] = __expf(v[j].y - m);
        e[j][2] = __expf(v[j].z - m); e[j][3] = __expf(v[j].w - m);
        s += (e[j][0] + e[j][1]) + (e[j][2] + e[j][3]);
    }
    #pragma unroll
    for (int off = 16; off; off >>= 1)
        s += __shfl_xor_sync(0xffffffffu, s, off);
    float inv = 1.0f / s;

    bf16* o = out + (size_t)row * DD;
    #pragma unroll
    for (int j = 0; j < 6; j++) {
        uint2 w = make_uint2(pack_bf2(e[j][0] * inv, e[j][1] * inv),
                             pack_bf2(e[j][2] * inv, e[j][3] * inv));
        *(uint2*)(o + (j * 32 + lane) * 4) = w;
    }
}

// ---------------------------------------------------------------------------
// Column softmax over tokens -> bf16, fused over two tensors (blockIdx.z).
// ---------------------------------------------------------------------------
__global__ void col_softmax2_k(const float* __restrict__ in2, bf16* __restrict__ o2,
                               const float* __restrict__ in3, bf16* __restrict__ o3) {
    const float* in = blockIdx.z ? in3 : in2;
    bf16* out = blockIdx.z ? o3 : o2;
    int b = blockIdx.y;
    int dl = threadIdx.x & 31;
    int d = blockIdx.x * 32 + dl;
    int lane = threadIdx.x >> 5;

    const float* p = in + (size_t)b * NN * DD + d;
    float m = -INFINITY, s = 0.0f;
    for (int n = lane; n < NN; n += 8) {
        float v = p[(size_t)n * DD];
        float mn = fmaxf(m, v);
        s = s * __expf(m - mn) + __expf(v - mn);
        m = mn;
    }

    __shared__ float sm[8][32], ss[8][32];
    sm[lane][dl] = m;
    ss[lane][dl] = s;
    __syncthreads();
    if (threadIdx.x < 32) {
        float M = sm[0][dl], S = ss[0][dl];
        #pragma unroll
        for (int i = 1; i < 8; i++) {
            float mi = sm[i][dl], si = ss[i][dl];
            float mn = fmaxf(M, mi);
            S = S * __expf(M - mn) + si * __expf(mi - mn);
            M = mn;
        }
        sm[0][dl] = M;
        ss[0][dl] = 1.0f / S;
    }
    __syncthreads();
    float M = sm[0][dl], invS = ss[0][dl];

    size_t ob = (size_t)b * NN * DD + d;
    for (int n = lane; n < NN; n += 8)
        out[ob + (size_t)n * DD] = __float2bfloat16_rn(__expf(p[(size_t)n * DD] - M) * invS);
}

// ---------------------------------------------------------------------------
// Fused fp32 -> bf16 cast of W1, W2, x (one launch)
// ---------------------------------------------------------------------------
#define W4 (DD * DD / 4)
#define X4 (BB * NN * DD / 4)
__global__ void cast_all_k(const float* __restrict__ W1, const float* __restrict__ W2,
                           const float* __restrict__ x,
                           bf16* __restrict__ Wh, bf16* __restrict__ xh) {
    int i = blockIdx.x * blockDim.x + threadIdx.x;
    const float* src;
    bf16* dst;
    int j;
    if (i < W4)            { src = W1; dst = Wh;                 j = i; }
    else if (i < 2 * W4)   { src = W2; dst = Wh + (size_t)DD*DD; j = i - W4; }
    else if (i < 2*W4+X4)  { src = x;  dst = xh;                 j = i - 2 * W4; }
    else return;
    float4 v = ((const float4*)src)[j];
    ((uint2*)dst)[j] = make_uint2(pack_bf2(v.x, v.y), pack_bf2(v.z, v.w));
}

// ---------------------------------------------------------------------------
// Single-term bf16 GEMM: C[m][n] = sum_k A[m][k] * B[n][k]  (fp32 accum)
// CTA 128x128, k-tile 32, 8 warps, cp.async 3-stage, occupancy 2.
// TR: operands [k][mn] via ldmatrix.trans. dualz: blockIdx.z >= BB selects
// second (A2,B2,C2) problem (independent GEMM). kt2>0: concat K (A2,B2).
// mode 0: C -> bf16. mode 1: fp32 out = f*(acc+bias)+x.
// ---------------------------------------------------------------------------
#define TILEB  8192
#define STAGE  (2 * TILEB)
#define NSTG   3
#define SMEMSZ (NSTG * STAGE)

template <bool TR>
__global__ __launch_bounds__(256, 2)
void gemm1t_k(const bf16* __restrict__ Ah1, const bf16* __restrict__ Bh1, int kt1,
              const bf16* __restrict__ Ah2, const bf16* __restrict__ Bh2, int kt2,
              int dualz,
              long sA1, long sB1, long sA2, long sB2,
              int lda1, int ldb1, int lda2, int ldb2,
              int mode,
              float* __restrict__ Cf, bf16* __restrict__ Ch, bf16* __restrict__ Ch2,
              long sC, int ldc,
              const float* __restrict__ bias1, const float* __restrict__ bias2,
              const float* __restrict__ gate, const float* __restrict__ xres)
{
    extern __shared__ char sm[];
    uint32_t smb = smem_u32(sm);
    int tid = threadIdx.x, lane = tid & 31, wid = tid >> 5;
    int b = blockIdx.z, n0 = blockIdx.x * 128, m0 = blockIdx.y * 128;
    int wm = wid & 3, wn = wid >> 2;

    const bf16* A1p = Ah1;
    const bf16* B1p = Bh1;
    bf16* Chp = Ch;
    if (dualz && b >= BB) { A1p = Ah2; B1p = Bh2; Chp = Ch2; b -= BB; }

    const bf16 *Ab1, *Bb1, *Ab2 = 0, *Bb2 = 0;
    if (TR) {
        Ab1 = A1p + (size_t)b * sA1 + m0;
        Bb1 = B1p + (size_t)b * sB1 + n0;
        if (!dualz && Ah2) { Ab2 = Ah2 + (size_t)b * sA2 + m0; Bb2 = Bh2 + (size_t)b * sB2 + n0; }
    } else {
        Ab1 = A1p + (size_t)b * sA1 + (size_t)m0 * lda1;
        Bb1 = B1p + (size_t)b * sB1 + (size_t)n0 * ldb1;
        if (!dualz && Ah2) { Ab2 = Ah2 + (size_t)b * sA2 + (size_t)m0 * lda2;
                             Bb2 = Bh2 + (size_t)b * sB2 + (size_t)n0 * ldb2; }
    }
    int KT = kt1 + kt2;

    uint32_t d0off, d1off;
    int sr0, sc0, sr1, sc1;
    if (TR) {
        int q0 = tid, q1 = tid + 256;
        sr0 = q0 >> 4; sc0 = q0 & 15;
        sr1 = q1 >> 4; sc1 = q1 & 15;
        d0off = (uint32_t)sr0 * 256 + (uint32_t)((sc0 ^ (sr0 & 7)) << 4);
        d1off = (uint32_t)sr1 * 256 + (uint32_t)((sc1 ^ (sr1 & 7)) << 4);
    } else {
        int q0 = tid, q1 = tid + 256;
        sr0 = q0 >> 2; sc0 = q0 & 3;
        sr1 = q1 >> 2; sc1 = q1 & 3;
        d0off = (uint32_t)sr0 * 64 + (uint32_t)((sc0 ^ ((sr0 >> 1) & 3)) << 4);
        d1off = (uint32_t)sr1 * 64 + (uint32_t)((sc1 ^ ((sr1 >> 1) & 3)) << 4);
    }

    #define ISSUE_STAGE(s) do {                                                          \
        int _s = (s);                                                                    \
        const bf16 *ah, *bh; int la, lb;                                                 \
        if (_s < kt1) { ah = Ab1; bh = Bb1; la = lda1; lb = ldb1; }                      \
        else { ah = Ab2; bh = Bb2; la = lda2; lb = ldb2; _s -= kt1; }                    \
        uint32_t sb = smb + (uint32_t)(((s) % NSTG)) * STAGE;                            \
        if (TR) {                                                                        \
            size_t kb = (size_t)(_s * 32);                                               \
            cpa16(sb + d0off,         ah + (kb + sr0) * la + sc0 * 8);                   \
            cpa16(sb + d1off,         ah + (kb + sr1) * la + sc1 * 8);                   \
            cpa16(sb + TILEB + d0off, bh + (kb + sr0) * lb + sc0 * 8);                   \
            cpa16(sb + TILEB + d1off, bh + (kb + sr1) * lb + sc1 * 8);                   \
        } else {                                                                         \
            int ko = _s * 32;                                                            \
            cpa16(sb + d0off,         ah + (size_t)sr0 * la + ko + sc0 * 8);             \
            cpa16(sb + d1off,         ah + (size_t)sr1 * la + ko + sc1 * 8);             \
            cpa16(sb + TILEB + d0off, bh + (size_t)sr0 * lb + ko + sc0 * 8);             \
            cpa16(sb + TILEB + d1off, bh + (size_t)sr1 * lb + ko + sc1 * 8);             \
        }                                                                                \
        CP_COMMIT();                                                                     \
    } while (0)

    int rA = 0, cAq = 0, swA = 0, rB = 0, cBq = 0, swB = 0;
    int lrA = 0, chA0 = 0, lrB = 0, chB0 = 0, sx = 0;
    if (TR) {
        lrA  = (lane & 7) + ((lane >> 4) << 3);
        chA0 = wm * 4 + ((lane >> 3) & 1);
        lrB  = (lane & 7) + (((lane >> 3) & 1) << 3);
        chB0 = wn * 8 + ((lane >> 4) & 1);
        sx   = lane & 7;
    } else {
        rA  = wm * 32 + (lane & 7) + ((lane >> 3) & 1) * 8;
        cAq = lane >> 4;
        swA = (rA >> 1) & 3;
        rB  = wn * 64 + (lane & 7) + ((lane >> 4) & 1) * 8;
        cBq = (lane >> 3) & 1;
        swB = (rB >> 1) & 3;
    }

    float acc[2][8][4] = {};

    ISSUE_STAGE(0);
    ISSUE_STAGE(1);

    for (int kt = 0; kt < KT; kt++) {
        if (kt == KT - 1) asm volatile("cp.async.wait_group 0;" ::: "memory");
        else              asm volatile("cp.async.wait_group 1;" ::: "memory");
        __syncthreads();
        if (kt + 2 < KT) ISSUE_STAGE(kt + 2);

        uint32_t bA = smb + (uint32_t)(kt % NSTG) * STAGE;
        uint32_t bB = bA + TILEB;
        #pragma unroll
        for (int ks = 0; ks < 2; ks++) {
            uint32_t aH[2][4], bH[4][4];
            if (TR) {
                #pragma unroll
                for (int mi = 0; mi < 2; mi++)
                    ldsm4t(aH[mi], bA + (uint32_t)(lrA + ks * 16) * 256 +
                                   (uint32_t)(((chA0 + mi * 2) ^ sx) << 4));
                #pragma unroll
                for (int np = 0; np < 4; np++)
                    ldsm4t(bH[np], bB + (uint32_t)(lrB + ks * 16) * 256 +
                                   (uint32_t)(((chB0 + np * 2) ^ sx) << 4));
            } else {
                uint32_t offA = (uint32_t)rA * 64 + (uint32_t)(((ks * 2 + cAq) ^ swA) << 4);
                #pragma unroll
                for (int mi = 0; mi < 2; mi++)
                    ldsm4(aH[mi], bA + offA + mi * 1024);
                uint32_t offB = (uint32_t)rB * 64 + (uint32_t)(((ks * 2 + cBq) ^ swB) << 4);
                #pragma unroll
                for (int np = 0; np < 4; np++)
                    ldsm4(bH[np], bB + offB + np * 1024);
            }
            #pragma unroll
            for (int mi = 0; mi < 2; mi++)
                #pragma unroll
                for (int ni = 0; ni < 8; ni++)
                    mma16816(acc[mi][ni], aH[mi], &bH[ni >> 1][(ni & 1) * 2]);
        }
        __syncthreads();
    }

    int g = lane >> 2, t4 = lane & 3;
    float f = 0.0f;
    if (mode == 1) f = 1.0f / (1.0f + __expf(-gate[0]));

    #pragma unroll
    for (int mi = 0; mi < 2; mi++) {
        #pragma unroll
        for (int ni = 0; ni < 8; ni++) {
            int row0 = m0 + wm * 32 + mi * 16 + g;
            int col = n0 + wn * 64 + ni * 8 + t4 * 2;
            if (mode == 0) {
                size_t i0 = (size_t)b * sC + (size_t)row0 * ldc + col;
                size_t i1 = i0 + (size_t)8 * ldc;
                *(uint32_t*)(Chp + i0) = pack_bf2(acc[mi][ni][0], acc[mi][ni][1]);
                *(uint32_t*)(Chp + i1) = pack_bf2(acc[mi][ni][2], acc[mi][ni][3]);
            } else {
                float g1 = bias1[col] + bias2[col];
                float g2 = bias1[col + 1] + bias2[col + 1];
                const float* x0 = xres + (size_t)b * NN * DD + (size_t)row0 * DD + col;
                const float* x1 = x0 + (size_t)8 * DD;
                float2 xv0 = *(const float2*)x0;
                float2 xv1 = *(const float2*)x1;
                float* p0 = Cf + (size_t)b * sC + (size_t)row0 * ldc + col;
                float* p1 = p0 + (size_t)8 * ldc;
                *(float2*)p0 = make_float2(f * (acc[mi][ni][0] + g1) + xv0.x,
                                           f * (acc[mi][ni][1] + g2) + xv0.y);
                *(float2*)p1 = make_float2(f * (acc[mi][ni][2] + g1) + xv1.x,
                                           f * (acc[mi][ni][3] + g2) + xv1.y);
            }
        }
    }
    #undef ISSUE_STAGE
}

// ---------------------------------------------------------------------------
extern "C" void kernel_launch(void* const* d_in, const int* in_sizes, int n_in,
                              void* d_out, int out_size) {
    const float* x  = (const float*)d_in[0];
    const float* x2 = (const float*)d_in[1];
    const float* x3 = (const float*)d_in[2];
    const float* W1 = (const float*)d_in[3];
    const float* b1 = (const float*)d_in[4];
    const float* W2 = (const float*)d_in[5];
    const float* b2 = (const float*)d_in[6];
    const float* w  = (const float*)d_in[7];
    float* out = (float*)d_out;

    bf16 *K2h, *Q2h, *K3h, *Q3h, *S1h, *S2h, *MTh, *Wh, *xh;
    cudaGetSymbolAddress((void**)&K2h, g_K2h);
    cudaGetSymbolAddress((void**)&Q2h, g_Q2h);
    cudaGetSymbolAddress((void**)&K3h, g_K3h);
    cudaGetSymbolAddress((void**)&Q3h, g_Q3h);
    cudaGetSymbolAddress((void**)&S1h, g_S1h);
    cudaGetSymbolAddress((void**)&S2h, g_S2h);
    cudaGetSymbolAddress((void**)&MTh, g_MTh);
    cudaGetSymbolAddress((void**)&Wh,  g_Wh);
    cudaGetSymbolAddress((void**)&xh,  g_xh);

    cudaFuncSetAttribute(gemm1t_k<true>,  cudaFuncAttributeMaxDynamicSharedMemorySize, SMEMSZ);
    cudaFuncSetAttribute(gemm1t_k<false>, cudaFuncAttributeMaxDynamicSharedMemorySize, SMEMSZ);

    long sTok = (long)NN * DD;
    long sDD  = (long)DD * DD;

    // 1) fused bf16 casts (W1, W2, x)
    cast_all_k<<<(2 * W4 + X4 + 255) / 256, 256>>>(W1, W2, x, Wh, xh);

    // 2) fused row softmax (x2 -> K2h, x3 -> K3h), warp-per-row
    row_softmax2_k<<<2 * BB * NN / 8, 256>>>(x2, K2h, x3, K3h);

    // 3) fused col softmax (x2 -> Q2h, x3 -> Q3h)
    col_softmax2_k<<<dim3(DD / 32, BB, 2), 256>>>(x2, Q2h, x3, Q3h);

    // 4) fused attention GEMMs: S1 = K2^T@Q2, S2 = K3^T@Q3 (TR path, dualz)
    gemm1t_k<true><<<dim3(DD / 128, DD / 128, 2 * BB), 256, SMEMSZ>>>(
        K2h, Q2h, NN / 32, K3h, Q3h, 0, /*dualz=*/1,
        sTok, sTok, sTok, sTok, DD, DD, DD, DD,
        0, nullptr, S1h, S2h, sDD, DD,
        nullptr, nullptr, nullptr, nullptr);

    // 5) MT[e][d] = sum_k W1[e][k]*S1[d][k] + W2[e][k]*S2[d][k]
    gemm1t_k<false><<<dim3(DD / 128, DD / 128, BB), 256, SMEMSZ>>>(
        Wh, S1h, DD / 32, Wh + (size_t)DD * DD, S2h, DD / 32, /*dualz=*/0,
        0, sDD, 0, sDD, DD, DD, DD, DD,
        0, nullptr, MTh, nullptr, sDD, DD,
        nullptr, nullptr, nullptr, nullptr);

    // 6) out[n][e] = f*( sum_d x[n][d]*MT[e][d] + b1[e]+b2[e] ) + x[n][e]
    gemm1t_k<false><<<dim3(DD / 128, NN / 128, BB), 256, SMEMSZ>>>(
        xh, MTh, DD / 32, nullptr, nullptr, 0, /*dualz=*/0,
        sTok, sDD, 0, 0, DD, DD, 0, 0,
        1, out, nullptr, nullptr, sTok, DD,
        b1, b2, w, x);
}